// round 1
// baseline (speedup 1.0000x reference)
#include <cuda_runtime.h>

#define B_ 4
#define T_ 2048
#define C_ 1024
#define H_ 16
#define D_ 64
#define C3_ 3072

// Scratch (device globals: allocation-free per harness rules)
__device__ float g_qkv[(size_t)B_ * T_ * C3_];  // [B,T,3C]
__device__ float g_y[(size_t)B_ * T_ * C_];     // [B,T,C]

// ---------------------------------------------------------------------------
// NT GEMM: C[M,N] = A[M,K] @ W[N,K]^T   (both A and W are K-major row-major)
// 128x128 tile, BK=16, 256 threads, 8x8 micro-tile per thread.
// ---------------------------------------------------------------------------
__global__ __launch_bounds__(256)
void gemm_nt128(const float* __restrict__ A, const float* __restrict__ W,
                float* __restrict__ C, int M, int N, int K)
{
    const int BM = 128, BN = 128, BK = 16;
    __shared__ __align__(16) float As[BK][BM + 4];
    __shared__ __align__(16) float Bs[BK][BN + 4];

    const int tid = threadIdx.x;
    const int tx = tid & 15;        // 0..15 -> N
    const int ty = tid >> 4;        // 0..15 -> M
    const int m0 = blockIdx.y * BM;
    const int n0 = blockIdx.x * BN;

    float acc[8][8];
#pragma unroll
    for (int i = 0; i < 8; i++)
#pragma unroll
        for (int j = 0; j < 8; j++) acc[i][j] = 0.f;

    for (int k0 = 0; k0 < K; k0 += BK) {
        // Load A tile (128x16) and W tile (128x16), store K-major -> [k][m]
#pragma unroll
        for (int i = 0; i < 2; i++) {
            int c = tid + i * 256;          // 0..511 float4 chunks
            int row = c >> 2;               // 0..127
            int col4 = (c & 3) << 2;        // 0,4,8,12
            float4 va = *reinterpret_cast<const float4*>(
                A + (size_t)(m0 + row) * K + k0 + col4);
            As[col4 + 0][row] = va.x;
            As[col4 + 1][row] = va.y;
            As[col4 + 2][row] = va.z;
            As[col4 + 3][row] = va.w;
            float4 vb = *reinterpret_cast<const float4*>(
                W + (size_t)(n0 + row) * K + k0 + col4);
            Bs[col4 + 0][row] = vb.x;
            Bs[col4 + 1][row] = vb.y;
            Bs[col4 + 2][row] = vb.z;
            Bs[col4 + 3][row] = vb.w;
        }
        __syncthreads();

#pragma unroll
        for (int k = 0; k < BK; k++) {
            float a[8], b[8];
#pragma unroll
            for (int i = 0; i < 2; i++) {
                float4 t = *reinterpret_cast<const float4*>(&As[k][ty * 8 + i * 4]);
                a[i * 4 + 0] = t.x; a[i * 4 + 1] = t.y;
                a[i * 4 + 2] = t.z; a[i * 4 + 3] = t.w;
                float4 u = *reinterpret_cast<const float4*>(&Bs[k][tx * 8 + i * 4]);
                b[i * 4 + 0] = u.x; b[i * 4 + 1] = u.y;
                b[i * 4 + 2] = u.z; b[i * 4 + 3] = u.w;
            }
#pragma unroll
            for (int i = 0; i < 8; i++)
#pragma unroll
                for (int j = 0; j < 8; j++)
                    acc[i][j] += a[i] * b[j];
        }
        __syncthreads();
    }

#pragma unroll
    for (int i = 0; i < 8; i++) {
#pragma unroll
        for (int j = 0; j < 2; j++) {
            float4 t = make_float4(acc[i][j * 4 + 0], acc[i][j * 4 + 1],
                                   acc[i][j * 4 + 2], acc[i][j * 4 + 3]);
            *reinterpret_cast<float4*>(
                C + (size_t)(m0 + ty * 8 + i) * N + n0 + tx * 8 + j * 4) = t;
        }
    }
}

// ---------------------------------------------------------------------------
// Flash attention (causal, online softmax). One query row per thread.
// Block: 128 threads = 128 query rows. KV staged in SMEM in 32-row tiles.
// K/V reads from SMEM are warp-uniform -> broadcast, conflict-free.
// ---------------------------------------------------------------------------
__global__ __launch_bounds__(128)
void flash_attn()
{
    const int BM = 128, BN = 32;
    const int b = blockIdx.z;
    const int h = blockIdx.y;
    // Reverse tile order so the heaviest (longest causal span) blocks start first
    const int qt = gridDim.x - 1 - blockIdx.x;
    const int tid = threadIdx.x;
    const int q = qt * BM + tid;

    __shared__ __align__(16) float Ks[BN][D_];
    __shared__ __align__(16) float Vs[BN][D_];

    float qreg[D_];
    const float* qp = g_qkv + (size_t)(b * T_ + q) * C3_ + h * D_;
#pragma unroll
    for (int i = 0; i < D_ / 4; i++) {
        float4 t = *reinterpret_cast<const float4*>(qp + i * 4);
        qreg[i * 4 + 0] = t.x; qreg[i * 4 + 1] = t.y;
        qreg[i * 4 + 2] = t.z; qreg[i * 4 + 3] = t.w;
    }

    float acc[D_];
#pragma unroll
    for (int d = 0; d < D_; d++) acc[d] = 0.f;
    float mrow = -1e30f, lrow = 0.f;
    const float scale = 0.125f;  // 1/sqrt(64)

    const int kend = qt * BM + BM;  // causal: keys < end of this q tile
    for (int j0 = 0; j0 < kend; j0 += BN) {
        // Cooperative load of K and V tiles (32 x 64 floats each)
#pragma unroll
        for (int i = 0; i < 4; i++) {
            int c = tid + i * 128;           // 0..511 float4 chunks
            int row = c >> 4;                // 16 float4 per row
            int col = (c & 15) << 2;
            const float* kp = g_qkv + (size_t)(b * T_ + j0 + row) * C3_
                              + C_ + h * D_ + col;
            *reinterpret_cast<float4*>(&Ks[row][col]) =
                *reinterpret_cast<const float4*>(kp);
            *reinterpret_cast<float4*>(&Vs[row][col]) =
                *reinterpret_cast<const float4*>(kp + C_);
        }
        __syncthreads();

        float s[BN];
        float tmax = -1e30f;
#pragma unroll
        for (int j = 0; j < BN; j++) {
            float sum = 0.f;
#pragma unroll
            for (int d = 0; d < D_; d++) sum += qreg[d] * Ks[j][d];
            sum *= scale;
            sum = (j0 + j <= q) ? sum : -1e30f;  // causal mask
            s[j] = sum;
            tmax = fmaxf(tmax, sum);
        }

        const float mnew = fmaxf(mrow, tmax);
        const float corr = __expf(mrow - mnew);
        lrow *= corr;
#pragma unroll
        for (int d = 0; d < D_; d++) acc[d] *= corr;

#pragma unroll
        for (int j = 0; j < BN; j++) {
            const float p = __expf(s[j] - mnew);
            lrow += p;
#pragma unroll
            for (int d = 0; d < D_; d++) acc[d] += p * Vs[j][d];
        }
        mrow = mnew;
        __syncthreads();
    }

    const float inv = 1.f / lrow;
    float* yp = g_y + (size_t)(b * T_ + q) * C_ + h * D_;
#pragma unroll
    for (int i = 0; i < D_ / 4; i++) {
        float4 t = make_float4(acc[i * 4 + 0] * inv, acc[i * 4 + 1] * inv,
                               acc[i * 4 + 2] * inv, acc[i * 4 + 3] * inv);
        *reinterpret_cast<float4*>(yp + i * 4) = t;
    }
}

// ---------------------------------------------------------------------------
// Launch: qkv = x @ w_attn^T ; flash attention ; out = y @ w_proj^T
// ---------------------------------------------------------------------------
extern "C" void kernel_launch(void* const* d_in, const int* in_sizes, int n_in,
                              void* d_out, int out_size)
{
    const float* x      = (const float*)d_in[0];  // [B,T,C]
    const float* w_attn = (const float*)d_in[1];  // [3C,C]
    const float* w_proj = (const float*)d_in[2];  // [C,C]
    float* out = (float*)d_out;                   // [B,T,C]

    float *qkv, *y;
    cudaGetSymbolAddress((void**)&qkv, g_qkv);
    cudaGetSymbolAddress((void**)&y, g_y);

    // 1) QKV projection: M=8192, N=3072, K=1024
    dim3 g1(C3_ / 128, (B_ * T_) / 128);
    gemm_nt128<<<g1, 256>>>(x, w_attn, qkv, B_ * T_, C3_, C_);

    // 2) Causal flash attention over g_qkv -> g_y
    dim3 g2(T_ / 128, H_, B_);
    flash_attn<<<g2, 128>>>();

    // 3) Output projection: M=8192, N=1024, K=1024
    dim3 g3(C_ / 128, (B_ * T_) / 128);
    gemm_nt128<<<g3, 256>>>(y, w_proj, out, B_ * T_, C_, C_);
}

// round 4
// speedup vs baseline: 1.3386x; 1.3386x over previous
#include <cuda_runtime.h>
#include <cuda_bf16.h>
#include <cstdint>

#define B_ 4
#define T_ 2048
#define C_ 1024
#define H_ 16
#define D_ 64
#define C3_ 3072
#define M_ROWS (B_ * T_)

// ---------------- scratch (device globals: allocation-free) ----------------
__device__ float g_qkv[(size_t)B_ * T_ * C3_];   // [B,T,3C] fp32
__device__ float g_y[(size_t)B_ * T_ * C_];      // [B,T,C]  fp32
__device__ __nv_bfloat16 g_xhi[(size_t)M_ROWS * C_];
__device__ __nv_bfloat16 g_xlo[(size_t)M_ROWS * C_];
__device__ __nv_bfloat16 g_wahi[(size_t)C3_ * C_];
__device__ __nv_bfloat16 g_walo[(size_t)C3_ * C_];
__device__ __nv_bfloat16 g_wphi[(size_t)C_ * C_];
__device__ __nv_bfloat16 g_wplo[(size_t)C_ * C_];
__device__ __nv_bfloat16 g_yhi[(size_t)M_ROWS * C_];
__device__ __nv_bfloat16 g_ylo[(size_t)M_ROWS * C_];

// ---------------- helpers ----------------
__device__ __forceinline__ uint32_t smem_u32(const void* p) {
    uint32_t a;
    asm("{ .reg .u64 t; cvta.to.shared.u64 t, %1; cvt.u32.u64 %0, t; }"
        : "=r"(a) : "l"(p));
    return a;
}

__device__ __forceinline__ void cp_async16(uint32_t dst, const void* src) {
    asm volatile("cp.async.cg.shared.global [%0], [%1], 16;" :: "r"(dst), "l"(src));
}
__device__ __forceinline__ void cp_commit() {
    asm volatile("cp.async.commit_group;" ::: "memory");
}
__device__ __forceinline__ void cp_wait1() {
    asm volatile("cp.async.wait_group 1;" ::: "memory");
}
__device__ __forceinline__ void cp_wait0() {
    asm volatile("cp.async.wait_group 0;" ::: "memory");
}

__device__ __forceinline__ void ldmx4(uint32_t& r0, uint32_t& r1, uint32_t& r2,
                                      uint32_t& r3, uint32_t addr) {
    asm volatile("ldmatrix.sync.aligned.m8n8.x4.shared.b16 {%0,%1,%2,%3}, [%4];"
                 : "=r"(r0), "=r"(r1), "=r"(r2), "=r"(r3) : "r"(addr));
}

__device__ __forceinline__ void mma16816(float& d0, float& d1, float& d2, float& d3,
                                         uint32_t a0, uint32_t a1, uint32_t a2, uint32_t a3,
                                         uint32_t b0, uint32_t b1) {
    asm volatile("mma.sync.aligned.m16n8k16.row.col.f32.bf16.bf16.f32 "
                 "{%0,%1,%2,%3}, {%4,%5,%6,%7}, {%8,%9}, {%0,%1,%2,%3};"
                 : "+f"(d0), "+f"(d1), "+f"(d2), "+f"(d3)
                 : "r"(a0), "r"(a1), "r"(a2), "r"(a3), "r"(b0), "r"(b1));
}

// ---------------- fp32 -> (bf16 hi, bf16 lo) split ----------------
__global__ __launch_bounds__(256)
void split_bf16(const float4* __restrict__ in, __nv_bfloat162* __restrict__ hi,
                __nv_bfloat162* __restrict__ lo, int n4)
{
    int i = blockIdx.x * 256 + threadIdx.x;
    if (i >= n4) return;
    float4 v = in[i];
    __nv_bfloat16 h0 = __float2bfloat16(v.x);
    __nv_bfloat16 h1 = __float2bfloat16(v.y);
    __nv_bfloat16 h2 = __float2bfloat16(v.z);
    __nv_bfloat16 h3 = __float2bfloat16(v.w);
    __nv_bfloat16 l0 = __float2bfloat16(v.x - __bfloat162float(h0));
    __nv_bfloat16 l1 = __float2bfloat16(v.y - __bfloat162float(h1));
    __nv_bfloat16 l2 = __float2bfloat16(v.z - __bfloat162float(h2));
    __nv_bfloat16 l3 = __float2bfloat16(v.w - __bfloat162float(h3));
    hi[2 * i + 0] = __nv_bfloat162(h0, h1);
    hi[2 * i + 1] = __nv_bfloat162(h2, h3);
    lo[2 * i + 0] = __nv_bfloat162(l0, l1);
    lo[2 * i + 1] = __nv_bfloat162(l2, l3);
}

// ---------------- mma.sync GEMM: C[M,N] = A[M,K] @ W[N,K]^T (3xBF16) -------
// CTA 128x128, BK=64. 8 warps (2 M x 4 N), warp tile 64x32.
// SMEM: per stage {Ahi, Alo, Bhi, Blo}, each 128 rows x 128B, SW128 swizzle.
#define TILE_B 16384
#define STAGE_B (4 * TILE_B)
#define SMEM_TOTAL (2 * STAGE_B)

// swizzled byte offset inside a tile: row-major 128B rows, xor bits 4-6 by row&7
__device__ __forceinline__ uint32_t swz(uint32_t row, uint32_t kb) {
    return row * 128u + (kb ^ ((row & 7u) * 16u));
}

__global__ __launch_bounds__(256, 1)
void gemm_mma(const __nv_bfloat16* __restrict__ Ahi, const __nv_bfloat16* __restrict__ Alo,
              const __nv_bfloat16* __restrict__ Bhi, const __nv_bfloat16* __restrict__ Blo,
              float* __restrict__ Cout, int M, int N, int K)
{
    extern __shared__ char smem[];
    const uint32_t sbase = smem_u32(smem);
    const int tid = threadIdx.x;
    const int wid = tid >> 5;
    const int lane = tid & 31;
    const int wm = wid & 1;          // 0..1 -> M offset 0/64
    const int wn = wid >> 1;         // 0..3 -> N offset 0/32/64/96
    const size_t m0 = (size_t)blockIdx.y * 128;
    const size_t n0 = (size_t)blockIdx.x * 128;

    const int quad = lane >> 3;
    const int qr = lane & 7;

    float acc[4][4][4];
#pragma unroll
    for (int i = 0; i < 4; i++)
#pragma unroll
        for (int j = 0; j < 4; j++)
#pragma unroll
            for (int r = 0; r < 4; r++) acc[i][j][r] = 0.f;

    const int NCH = K >> 6;

    // --- async tile loader: 4 tiles x 1024 16B-chunks, 16 chunks/thread ---
    auto issue_chunk = [&](int ch, int stage) {
        const int k0 = ch * 64;
        char* dstA_hi = smem + stage * STAGE_B + 0 * TILE_B;
        char* dstA_lo = smem + stage * STAGE_B + 1 * TILE_B;
        char* dstB_hi = smem + stage * STAGE_B + 2 * TILE_B;
        char* dstB_lo = smem + stage * STAGE_B + 3 * TILE_B;
#pragma unroll
        for (int it = 0; it < 4; it++) {
            int idx = it * 256 + tid;        // 0..1023
            uint32_t row = idx >> 3;
            uint32_t c16 = idx & 7;
            uint32_t off = swz(row, c16 * 16u);
            size_t akoff = (m0 + row) * (size_t)K + k0 + c16 * 8;
            size_t bkoff = (n0 + row) * (size_t)K + k0 + c16 * 8;
            cp_async16(smem_u32(dstA_hi + off), Ahi + akoff);
            cp_async16(smem_u32(dstA_lo + off), Alo + akoff);
            cp_async16(smem_u32(dstB_hi + off), Bhi + bkoff);
            cp_async16(smem_u32(dstB_lo + off), Blo + bkoff);
        }
        cp_commit();
    };

    issue_chunk(0, 0);

    for (int ch = 0; ch < NCH; ch++) {
        const int s = ch & 1;
        if (ch + 1 < NCH) {
            issue_chunk(ch + 1, s ^ 1);
            cp_wait1();
        } else {
            cp_wait0();
        }
        __syncthreads();

        const uint32_t tAh = sbase + s * STAGE_B + 0 * TILE_B;
        const uint32_t tAl = sbase + s * STAGE_B + 1 * TILE_B;
        const uint32_t tBh = sbase + s * STAGE_B + 2 * TILE_B;
        const uint32_t tBl = sbase + s * STAGE_B + 3 * TILE_B;

#pragma unroll
        for (int kk = 0; kk < 4; kk++) {
            const uint32_t kb = kk * 32;
            // A fragments: per lane address for ldmatrix.x4 over 16x16
            uint32_t ah[4][4], al[4][4];
#pragma unroll
            for (int mi = 0; mi < 4; mi++) {
                uint32_t arow = wm * 64 + mi * 16 + (quad & 1) * 8 + qr;
                uint32_t akb = kb + (quad >> 1) * 16;
                uint32_t o = swz(arow, akb);
                ldmx4(ah[mi][0], ah[mi][1], ah[mi][2], ah[mi][3], tAh + o);
                ldmx4(al[mi][0], al[mi][1], al[mi][2], al[mi][3], tAl + o);
            }
            // B fragments: x4 covers two n-frags (8 wide each), full k16
            uint32_t bh[4][2], bl[4][2];
#pragma unroll
            for (int bi = 0; bi < 2; bi++) {
                uint32_t brow = wn * 32 + bi * 16 + (quad >> 1) * 8 + qr;
                uint32_t bkb = kb + (quad & 1) * 16;
                uint32_t o = swz(brow, bkb);
                ldmx4(bh[bi * 2][0], bh[bi * 2][1], bh[bi * 2 + 1][0], bh[bi * 2 + 1][1],
                      tBh + o);
                ldmx4(bl[bi * 2][0], bl[bi * 2][1], bl[bi * 2 + 1][0], bl[bi * 2 + 1][1],
                      tBl + o);
            }
            // 3-term split MMAs
#pragma unroll
            for (int mi = 0; mi < 4; mi++) {
#pragma unroll
                for (int ni = 0; ni < 4; ni++) {
                    float* d = acc[mi][ni];
                    mma16816(d[0], d[1], d[2], d[3],
                             ah[mi][0], ah[mi][1], ah[mi][2], ah[mi][3],
                             bh[ni][0], bh[ni][1]);
                    mma16816(d[0], d[1], d[2], d[3],
                             ah[mi][0], ah[mi][1], ah[mi][2], ah[mi][3],
                             bl[ni][0], bl[ni][1]);
                    mma16816(d[0], d[1], d[2], d[3],
                             al[mi][0], al[mi][1], al[mi][2], al[mi][3],
                             bh[ni][0], bh[ni][1]);
                }
            }
        }
        __syncthreads();
    }

    // --- epilogue: fp32 direct to global ---
    const int g = lane >> 2;
    const int ti = lane & 3;
#pragma unroll
    for (int mi = 0; mi < 4; mi++) {
#pragma unroll
        for (int ni = 0; ni < 4; ni++) {
            size_t row = m0 + wm * 64 + mi * 16 + g;
            size_t col = n0 + wn * 32 + ni * 8 + 2 * ti;
            float2 lo2 = make_float2(acc[mi][ni][0], acc[mi][ni][1]);
            float2 hi2 = make_float2(acc[mi][ni][2], acc[mi][ni][3]);
            *reinterpret_cast<float2*>(Cout + row * N + col) = lo2;
            *reinterpret_cast<float2*>(Cout + (row + 8) * N + col) = hi2;
        }
    }
}

// ---------------- Flash attention (fp32, unchanged from R1) ----------------
__global__ __launch_bounds__(128)
void flash_attn()
{
    const int BM = 128, BN = 32;
    const int b = blockIdx.z;
    const int h = blockIdx.y;
    const int qt = gridDim.x - 1 - blockIdx.x;
    const int tid = threadIdx.x;
    const int q = qt * BM + tid;

    __shared__ __align__(16) float Ks[BN][D_];
    __shared__ __align__(16) float Vs[BN][D_];

    float qreg[D_];
    const float* qp = g_qkv + (size_t)(b * T_ + q) * C3_ + h * D_;
#pragma unroll
    for (int i = 0; i < D_ / 4; i++) {
        float4 t = *reinterpret_cast<const float4*>(qp + i * 4);
        qreg[i * 4 + 0] = t.x; qreg[i * 4 + 1] = t.y;
        qreg[i * 4 + 2] = t.z; qreg[i * 4 + 3] = t.w;
    }

    float acc[D_];
#pragma unroll
    for (int d = 0; d < D_; d++) acc[d] = 0.f;
    float mrow = -1e30f, lrow = 0.f;
    const float scale = 0.125f;

    const int kend = qt * BM + BM;
    for (int j0 = 0; j0 < kend; j0 += BN) {
#pragma unroll
        for (int i = 0; i < 4; i++) {
            int c = tid + i * 128;
            int row = c >> 4;
            int col = (c & 15) << 2;
            const float* kp = g_qkv + (size_t)(b * T_ + j0 + row) * C3_
                              + C_ + h * D_ + col;
            *reinterpret_cast<float4*>(&Ks[row][col]) =
                *reinterpret_cast<const float4*>(kp);
            *reinterpret_cast<float4*>(&Vs[row][col]) =
                *reinterpret_cast<const float4*>(kp + C_);
        }
        __syncthreads();

        float s[BN];
        float tmax = -1e30f;
#pragma unroll
        for (int j = 0; j < BN; j++) {
            float sum = 0.f;
#pragma unroll
            for (int d = 0; d < D_; d++) sum += qreg[d] * Ks[j][d];
            sum *= scale;
            sum = (j0 + j <= q) ? sum : -1e30f;
            s[j] = sum;
            tmax = fmaxf(tmax, sum);
        }

        const float mnew = fmaxf(mrow, tmax);
        const float corr = __expf(mrow - mnew);
        lrow *= corr;
#pragma unroll
        for (int d = 0; d < D_; d++) acc[d] *= corr;

#pragma unroll
        for (int j = 0; j < BN; j++) {
            const float p = __expf(s[j] - mnew);
            lrow += p;
#pragma unroll
            for (int d = 0; d < D_; d++) acc[d] += p * Vs[j][d];
        }
        mrow = mnew;
        __syncthreads();
    }

    const float inv = 1.f / lrow;
    float* yp = g_y + (size_t)(b * T_ + q) * C_ + h * D_;
#pragma unroll
    for (int i = 0; i < D_ / 4; i++) {
        float4 t = make_float4(acc[i * 4 + 0] * inv, acc[i * 4 + 1] * inv,
                               acc[i * 4 + 2] * inv, acc[i * 4 + 3] * inv);
        *reinterpret_cast<float4*>(yp + i * 4) = t;
    }
}

// ---------------- launch ----------------
extern "C" void kernel_launch(void* const* d_in, const int* in_sizes, int n_in,
                              void* d_out, int out_size)
{
    const float* x      = (const float*)d_in[0];
    const float* w_attn = (const float*)d_in[1];
    const float* w_proj = (const float*)d_in[2];
    float* out = (float*)d_out;

    float *qkv, *y;
    __nv_bfloat16 *xhi, *xlo, *wahi, *walo, *wphi, *wplo, *yhi, *ylo;
    cudaGetSymbolAddress((void**)&qkv, g_qkv);
    cudaGetSymbolAddress((void**)&y, g_y);
    cudaGetSymbolAddress((void**)&xhi, g_xhi);
    cudaGetSymbolAddress((void**)&xlo, g_xlo);
    cudaGetSymbolAddress((void**)&wahi, g_wahi);
    cudaGetSymbolAddress((void**)&walo, g_walo);
    cudaGetSymbolAddress((void**)&wphi, g_wphi);
    cudaGetSymbolAddress((void**)&wplo, g_wplo);
    cudaGetSymbolAddress((void**)&yhi, g_yhi);
    cudaGetSymbolAddress((void**)&ylo, g_ylo);

    cudaFuncSetAttribute(gemm_mma, cudaFuncAttributeMaxDynamicSharedMemorySize, SMEM_TOTAL);

    // splits
    {
        int n4 = M_ROWS * C_ / 4;
        split_bf16<<<(n4 + 255) / 256, 256>>>((const float4*)x,
            (__nv_bfloat162*)xhi, (__nv_bfloat162*)xlo, n4);
    }
    {
        int n4 = C3_ * C_ / 4;
        split_bf16<<<(n4 + 255) / 256, 256>>>((const float4*)w_attn,
            (__nv_bfloat162*)wahi, (__nv_bfloat162*)walo, n4);
    }
    {
        int n4 = C_ * C_ / 4;
        split_bf16<<<(n4 + 255) / 256, 256>>>((const float4*)w_proj,
            (__nv_bfloat162*)wphi, (__nv_bfloat162*)wplo, n4);
    }

    // 1) QKV: [8192,3072] = x @ w_attn^T
    {
        dim3 g(C3_ / 128, M_ROWS / 128);
        gemm_mma<<<g, 256, SMEM_TOTAL>>>(xhi, xlo, wahi, walo, qkv, M_ROWS, C3_, C_);
    }

    // 2) attention
    {
        dim3 g(T_ / 128, H_, B_);
        flash_attn<<<g, 128>>>();
    }

    // 3) split y, then out = y @ w_proj^T
    {
        int n4 = M_ROWS * C_ / 4;
        split_bf16<<<(n4 + 255) / 256, 256>>>((const float4*)y,
            (__nv_bfloat162*)yhi, (__nv_bfloat162*)ylo, n4);
    }
    {
        dim3 g(C_ / 128, M_ROWS / 128);
        gemm_mma<<<g, 256, SMEM_TOTAL>>>(yhi, ylo, wphi, wplo, out, M_ROWS, C_, C_);
    }
}

// round 9
// speedup vs baseline: 3.9687x; 2.9648x over previous
#include <cuda_runtime.h>
#include <cuda_bf16.h>
#include <cstdint>

#define B_ 4
#define T_ 2048
#define C_ 1024
#define H_ 16
#define D_ 64
#define C3_ 3072
#define M_ROWS (B_ * T_)

// ---------------- scratch (device globals: allocation-free) ----------------
__device__ __nv_bfloat16 g_xhi[(size_t)M_ROWS * C_];
__device__ __nv_bfloat16 g_xlo[(size_t)M_ROWS * C_];
__device__ __nv_bfloat16 g_wahi[(size_t)C3_ * C_];
__device__ __nv_bfloat16 g_walo[(size_t)C3_ * C_];
__device__ __nv_bfloat16 g_wphi[(size_t)C_ * C_];
__device__ __nv_bfloat16 g_wplo[(size_t)C_ * C_];
__device__ __nv_bfloat16 g_qkvh[(size_t)M_ROWS * C3_];
__device__ __nv_bfloat16 g_qkvl[(size_t)M_ROWS * C3_];
__device__ __nv_bfloat16 g_yhi[(size_t)M_ROWS * C_];
__device__ __nv_bfloat16 g_ylo[(size_t)M_ROWS * C_];

// ---------------- helpers ----------------
__device__ __forceinline__ uint32_t smem_u32(const void* p) {
    uint32_t a;
    asm("{ .reg .u64 t; cvta.to.shared.u64 t, %1; cvt.u32.u64 %0, t; }"
        : "=r"(a) : "l"(p));
    return a;
}
__device__ __forceinline__ void cp_async16(uint32_t dst, const void* src) {
    asm volatile("cp.async.cg.shared.global [%0], [%1], 16;" :: "r"(dst), "l"(src));
}
__device__ __forceinline__ void cp_commit() {
    asm volatile("cp.async.commit_group;" ::: "memory");
}
__device__ __forceinline__ void cp_wait1() {
    asm volatile("cp.async.wait_group 1;" ::: "memory");
}
__device__ __forceinline__ void cp_wait0() {
    asm volatile("cp.async.wait_group 0;" ::: "memory");
}
__device__ __forceinline__ void ldmx4(uint32_t& r0, uint32_t& r1, uint32_t& r2,
                                      uint32_t& r3, uint32_t addr) {
    asm volatile("ldmatrix.sync.aligned.m8n8.x4.shared.b16 {%0,%1,%2,%3}, [%4];"
                 : "=r"(r0), "=r"(r1), "=r"(r2), "=r"(r3) : "r"(addr));
}
__device__ __forceinline__ void ldmx4t(uint32_t& r0, uint32_t& r1, uint32_t& r2,
                                       uint32_t& r3, uint32_t addr) {
    asm volatile("ldmatrix.sync.aligned.m8n8.x4.trans.shared.b16 {%0,%1,%2,%3}, [%4];"
                 : "=r"(r0), "=r"(r1), "=r"(r2), "=r"(r3) : "r"(addr));
}
__device__ __forceinline__ void mma16816(float& d0, float& d1, float& d2, float& d3,
                                         uint32_t a0, uint32_t a1, uint32_t a2, uint32_t a3,
                                         uint32_t b0, uint32_t b1) {
    asm volatile("mma.sync.aligned.m16n8k16.row.col.f32.bf16.bf16.f32 "
                 "{%0,%1,%2,%3}, {%4,%5,%6,%7}, {%8,%9}, {%0,%1,%2,%3};"
                 : "+f"(d0), "+f"(d1), "+f"(d2), "+f"(d3)
                 : "r"(a0), "r"(a1), "r"(a2), "r"(a3), "r"(b0), "r"(b1));
}
__device__ __forceinline__ float ex2(float x) {
    float y;
    asm("ex2.approx.ftz.f32 %0, %1;" : "=f"(y) : "f"(x));
    return y;
}
__device__ __forceinline__ uint32_t packbf2(float lo, float hi) {
    __nv_bfloat162 t = __floats2bfloat162_rn(lo, hi);  // .x = lo half
    return *reinterpret_cast<uint32_t*>(&t);
}
// swizzled byte offset: row-major 128B rows, xor bits 4-6 by row&7
__device__ __forceinline__ uint32_t swz(uint32_t row, uint32_t kb) {
    return row * 128u + (kb ^ ((row & 7u) * 16u));
}

// ---------------- fp32 -> (bf16 hi, bf16 lo) split ----------------
__global__ __launch_bounds__(256)
void split_bf16(const float4* __restrict__ in, __nv_bfloat162* __restrict__ hi,
                __nv_bfloat162* __restrict__ lo, int n4)
{
    int i = blockIdx.x * 256 + threadIdx.x;
    if (i >= n4) return;
    float4 v = in[i];
    __nv_bfloat16 h0 = __float2bfloat16(v.x);
    __nv_bfloat16 h1 = __float2bfloat16(v.y);
    __nv_bfloat16 h2 = __float2bfloat16(v.z);
    __nv_bfloat16 h3 = __float2bfloat16(v.w);
    hi[2 * i + 0] = __nv_bfloat162(h0, h1);
    hi[2 * i + 1] = __nv_bfloat162(h2, h3);
    lo[2 * i + 0] = __nv_bfloat162(__float2bfloat16(v.x - __bfloat162float(h0)),
                                   __float2bfloat16(v.y - __bfloat162float(h1)));
    lo[2 * i + 1] = __nv_bfloat162(__float2bfloat16(v.z - __bfloat162float(h2)),
                                   __float2bfloat16(v.w - __bfloat162float(h3)));
}

// ---------------- mma.sync GEMM: C = A @ W^T (3xBF16 split) -----------------
#define TILE_B 16384
#define STAGE_B (4 * TILE_B)
#define SMEM_TOTAL (2 * STAGE_B)

__global__ __launch_bounds__(256, 1)
void gemm_mma(const __nv_bfloat16* __restrict__ Ahi, const __nv_bfloat16* __restrict__ Alo,
              const __nv_bfloat16* __restrict__ Bhi, const __nv_bfloat16* __restrict__ Blo,
              float* __restrict__ Cout, __nv_bfloat16* __restrict__ Chi,
              __nv_bfloat16* __restrict__ Clo, int split_out, int M, int N, int K)
{
    extern __shared__ char smem[];
    const uint32_t sbase = smem_u32(smem);
    const int tid = threadIdx.x;
    const int wid = tid >> 5;
    const int lane = tid & 31;
    const int wm = wid & 1;
    const int wn = wid >> 1;
    const size_t m0 = (size_t)blockIdx.y * 128;
    const size_t n0 = (size_t)blockIdx.x * 128;
    const int quad = lane >> 3;
    const int qr = lane & 7;

    float acc[4][4][4];
#pragma unroll
    for (int i = 0; i < 4; i++)
#pragma unroll
        for (int j = 0; j < 4; j++)
#pragma unroll
            for (int r = 0; r < 4; r++) acc[i][j][r] = 0.f;

    const int NCH = K >> 6;

    auto issue_chunk = [&](int ch, int stage) {
        const int k0 = ch * 64;
        char* dA_hi = smem + stage * STAGE_B + 0 * TILE_B;
        char* dA_lo = smem + stage * STAGE_B + 1 * TILE_B;
        char* dB_hi = smem + stage * STAGE_B + 2 * TILE_B;
        char* dB_lo = smem + stage * STAGE_B + 3 * TILE_B;
#pragma unroll
        for (int it = 0; it < 4; it++) {
            int idx = it * 256 + tid;
            uint32_t row = idx >> 3;
            uint32_t c16 = idx & 7;
            uint32_t off = swz(row, c16 * 16u);
            size_t akoff = (m0 + row) * (size_t)K + k0 + c16 * 8;
            size_t bkoff = (n0 + row) * (size_t)K + k0 + c16 * 8;
            cp_async16(smem_u32(dA_hi + off), Ahi + akoff);
            cp_async16(smem_u32(dA_lo + off), Alo + akoff);
            cp_async16(smem_u32(dB_hi + off), Bhi + bkoff);
            cp_async16(smem_u32(dB_lo + off), Blo + bkoff);
        }
        cp_commit();
    };

    issue_chunk(0, 0);

    for (int ch = 0; ch < NCH; ch++) {
        const int s = ch & 1;
        if (ch + 1 < NCH) { issue_chunk(ch + 1, s ^ 1); cp_wait1(); }
        else cp_wait0();
        __syncthreads();

        const uint32_t tAh = sbase + s * STAGE_B + 0 * TILE_B;
        const uint32_t tAl = sbase + s * STAGE_B + 1 * TILE_B;
        const uint32_t tBh = sbase + s * STAGE_B + 2 * TILE_B;
        const uint32_t tBl = sbase + s * STAGE_B + 3 * TILE_B;

#pragma unroll
        for (int kk = 0; kk < 4; kk++) {
            const uint32_t kb = kk * 32;
            uint32_t ah[4][4], al[4][4];
#pragma unroll
            for (int mi = 0; mi < 4; mi++) {
                uint32_t arow = wm * 64 + mi * 16 + (quad & 1) * 8 + qr;
                uint32_t akb = kb + (quad >> 1) * 16;
                uint32_t o = swz(arow, akb);
                ldmx4(ah[mi][0], ah[mi][1], ah[mi][2], ah[mi][3], tAh + o);
                ldmx4(al[mi][0], al[mi][1], al[mi][2], al[mi][3], tAl + o);
            }
            uint32_t bh[4][2], bl[4][2];
#pragma unroll
            for (int bi = 0; bi < 2; bi++) {
                uint32_t brow = wn * 32 + bi * 16 + (quad >> 1) * 8 + qr;
                uint32_t bkb = kb + (quad & 1) * 16;
                uint32_t o = swz(brow, bkb);
                ldmx4(bh[bi * 2][0], bh[bi * 2][1], bh[bi * 2 + 1][0], bh[bi * 2 + 1][1],
                      tBh + o);
                ldmx4(bl[bi * 2][0], bl[bi * 2][1], bl[bi * 2 + 1][0], bl[bi * 2 + 1][1],
                      tBl + o);
            }
#pragma unroll
            for (int mi = 0; mi < 4; mi++) {
#pragma unroll
                for (int ni = 0; ni < 4; ni++) {
                    float* d = acc[mi][ni];
                    mma16816(d[0], d[1], d[2], d[3],
                             ah[mi][0], ah[mi][1], ah[mi][2], ah[mi][3],
                             bh[ni][0], bh[ni][1]);
                    mma16816(d[0], d[1], d[2], d[3],
                             ah[mi][0], ah[mi][1], ah[mi][2], ah[mi][3],
                             bl[ni][0], bl[ni][1]);
                    mma16816(d[0], d[1], d[2], d[3],
                             al[mi][0], al[mi][1], al[mi][2], al[mi][3],
                             bh[ni][0], bh[ni][1]);
                }
            }
        }
        __syncthreads();
    }

    const int g = lane >> 2;
    const int ti = lane & 3;
#pragma unroll
    for (int mi = 0; mi < 4; mi++) {
#pragma unroll
        for (int ni = 0; ni < 4; ni++) {
            size_t row = m0 + wm * 64 + mi * 16 + g;
            size_t col = n0 + wn * 32 + ni * 8 + 2 * ti;
            float* a = acc[mi][ni];
            if (split_out) {
                __nv_bfloat16 h0 = __float2bfloat16(a[0]);
                __nv_bfloat16 h1 = __float2bfloat16(a[1]);
                __nv_bfloat16 h2 = __float2bfloat16(a[2]);
                __nv_bfloat16 h3 = __float2bfloat16(a[3]);
                *reinterpret_cast<__nv_bfloat162*>(Chi + row * N + col) =
                    __nv_bfloat162(h0, h1);
                *reinterpret_cast<__nv_bfloat162*>(Chi + (row + 8) * N + col) =
                    __nv_bfloat162(h2, h3);
                *reinterpret_cast<__nv_bfloat162*>(Clo + row * N + col) =
                    __nv_bfloat162(__float2bfloat16(a[0] - __bfloat162float(h0)),
                                   __float2bfloat16(a[1] - __bfloat162float(h1)));
                *reinterpret_cast<__nv_bfloat162*>(Clo + (row + 8) * N + col) =
                    __nv_bfloat162(__float2bfloat16(a[2] - __bfloat162float(h2)),
                                   __float2bfloat16(a[3] - __bfloat162float(h3)));
            } else {
                *reinterpret_cast<float2*>(Cout + row * N + col) =
                    make_float2(a[0], a[1]);
                *reinterpret_cast<float2*>(Cout + (row + 8) * N + col) =
                    make_float2(a[2], a[3]);
            }
        }
    }
}

// ---------------- tensor-core flash attention (causal) ---------------------
// CTA: 128 q rows, 8 warps x 16 rows. KV tiles of 64, double-buffered.
// S = Q@K^T 3-term bf16 split; P split in regs; O = P@V 3-term.
#define AT_TILE 8192          // 64 rows x 128B
#define AT_STAGE (4 * AT_TILE)
#define AT_SMEM (2 * AT_STAGE)
#define SCALE_LOG2E 0.1803368801111204f   // (1/8) * log2(e)

__global__ __launch_bounds__(256, 1)
void flash_attn_mma(const __nv_bfloat16* __restrict__ qh,
                    const __nv_bfloat16* __restrict__ ql,
                    __nv_bfloat16* __restrict__ yh,
                    __nv_bfloat16* __restrict__ yl)
{
    extern __shared__ char smem[];
    const uint32_t sbase = smem_u32(smem);
    const int tid = threadIdx.x;
    const int wid = tid >> 5;
    const int lane = tid & 31;
    const int quad = lane >> 3;
    const int qr = lane & 7;
    const int b = blockIdx.z;
    const int h = blockIdx.y;
    const int qt = gridDim.x - 1 - blockIdx.x;
    const int q0 = qt * 128;
    const int nt = 2 * qt + 2;

    const size_t bbase = (size_t)(b * T_) * C3_;
    const __nv_bfloat16* qsh = qh + bbase + h * D_;          // Q hi
    const __nv_bfloat16* qsl = ql + bbase + h * D_;          // Q lo
    const __nv_bfloat16* ksh = qh + bbase + C_ + h * D_;     // K hi
    const __nv_bfloat16* ksl = ql + bbase + C_ + h * D_;
    const __nv_bfloat16* vsh = qh + bbase + 2 * C_ + h * D_; // V hi
    const __nv_bfloat16* vsl = ql + bbase + 2 * C_ + h * D_;

    // --- stage Q into smem (stage-1 region), KV tile0 into stage-0 ---
    {
        // Q: 128 rows x 8 chunks, hi then lo
#pragma unroll
        for (int it = 0; it < 8; it++) {
            const int half = it >> 2;
            const uint32_t r = (it & 3) * 32 + (tid >> 3);
            const uint32_t c16 = tid & 7;
            const __nv_bfloat16* src = (half == 0 ? qsh : qsl)
                                       + (size_t)(q0 + r) * C3_ + c16 * 8;
            cp_async16(sbase + AT_STAGE + half * 16384 + swz(r, c16 * 16u), src);
        }
        // KV tile 0 -> stage 0
#pragma unroll
        for (int it = 0; it < 8; it++) {
            const int tile = it >> 1;
            const uint32_t r = (it & 1) * 32 + (tid >> 3);
            const uint32_t c16 = tid & 7;
            const __nv_bfloat16* src =
                (tile == 0 ? ksh : tile == 1 ? ksl : tile == 2 ? vsh : vsl)
                + (size_t)r * C3_ + c16 * 8;
            cp_async16(sbase + tile * AT_TILE + swz(r, c16 * 16u), src);
        }
        cp_commit();
        cp_wait0();
    }
    __syncthreads();

    // --- Q fragments to registers ---
    uint32_t Qh[4][4], Ql[4][4];
#pragma unroll
    for (int kf = 0; kf < 4; kf++) {
        uint32_t arow = wid * 16 + (quad & 1) * 8 + qr;
        uint32_t akb = kf * 32 + (quad >> 1) * 16;
        uint32_t o = swz(arow, akb);
        ldmx4(Qh[kf][0], Qh[kf][1], Qh[kf][2], Qh[kf][3], sbase + AT_STAGE + o);
        ldmx4(Ql[kf][0], Ql[kf][1], Ql[kf][2], Ql[kf][3], sbase + AT_STAGE + 16384 + o);
    }
    __syncthreads();   // Q consumed; stage-1 region free

    auto issue_kv = [&](int t, int stage) {
        const int j0 = t * 64;
#pragma unroll
        for (int it = 0; it < 8; it++) {
            const int tile = it >> 1;
            const uint32_t r = (it & 1) * 32 + (tid >> 3);
            const uint32_t c16 = tid & 7;
            const __nv_bfloat16* src =
                (tile == 0 ? ksh : tile == 1 ? ksl : tile == 2 ? vsh : vsl)
                + (size_t)(j0 + r) * C3_ + c16 * 8;
            cp_async16(sbase + stage * AT_STAGE + tile * AT_TILE + swz(r, c16 * 16u), src);
        }
        cp_commit();
    };

    float O[8][4];
#pragma unroll
    for (int i = 0; i < 8; i++)
#pragma unroll
        for (int r = 0; r < 4; r++) O[i][r] = 0.f;
    float m0r = -1e30f, m1r = -1e30f, l0r = 0.f, l1r = 0.f;
    const int row_lo = q0 + wid * 16 + (lane >> 2);   // first row of frag

    for (int t = 0; t < nt; t++) {
        const int s = t & 1;
        if (t + 1 < nt) { issue_kv(t + 1, s ^ 1); cp_wait1(); }
        else cp_wait0();
        __syncthreads();

        const int j0 = t * 64;
        const uint32_t tKh = sbase + s * AT_STAGE + 0 * AT_TILE;
        const uint32_t tKl = sbase + s * AT_STAGE + 1 * AT_TILE;
        const uint32_t tVh = sbase + s * AT_STAGE + 2 * AT_TILE;
        const uint32_t tVl = sbase + s * AT_STAGE + 3 * AT_TILE;

        // ---- S = Q K^T ----
        float S[8][4];
#pragma unroll
        for (int i = 0; i < 8; i++)
#pragma unroll
            for (int r = 0; r < 4; r++) S[i][r] = 0.f;

#pragma unroll
        for (int kf = 0; kf < 4; kf++) {
            uint32_t bh[8][2], bl[8][2];
#pragma unroll
            for (int bi = 0; bi < 4; bi++) {
                uint32_t brow = bi * 16 + (quad >> 1) * 8 + qr;
                uint32_t bkb = kf * 32 + (quad & 1) * 16;
                uint32_t o = swz(brow, bkb);
                ldmx4(bh[bi * 2][0], bh[bi * 2][1], bh[bi * 2 + 1][0], bh[bi * 2 + 1][1],
                      tKh + o);
                ldmx4(bl[bi * 2][0], bl[bi * 2][1], bl[bi * 2 + 1][0], bl[bi * 2 + 1][1],
                      tKl + o);
            }
#pragma unroll
            for (int nf = 0; nf < 8; nf++) {
                mma16816(S[nf][0], S[nf][1], S[nf][2], S[nf][3],
                         Qh[kf][0], Qh[kf][1], Qh[kf][2], Qh[kf][3],
                         bh[nf][0], bh[nf][1]);
                mma16816(S[nf][0], S[nf][1], S[nf][2], S[nf][3],
                         Qh[kf][0], Qh[kf][1], Qh[kf][2], Qh[kf][3],
                         bl[nf][0], bl[nf][1]);
                mma16816(S[nf][0], S[nf][1], S[nf][2], S[nf][3],
                         Ql[kf][0], Ql[kf][1], Ql[kf][2], Ql[kf][3],
                         bh[nf][0], bh[nf][1]);
            }
        }

        // scale + causal mask
#pragma unroll
        for (int nf = 0; nf < 8; nf++)
#pragma unroll
            for (int r = 0; r < 4; r++) S[nf][r] *= SCALE_LOG2E;

        if (j0 + 63 > q0 + wid * 16) {
            const int kvb = j0 + 2 * (lane & 3);
#pragma unroll
            for (int nf = 0; nf < 8; nf++) {
                const int kv = kvb + nf * 8;
                if (kv     > row_lo)     S[nf][0] = -1e30f;
                if (kv + 1 > row_lo)     S[nf][1] = -1e30f;
                if (kv     > row_lo + 8) S[nf][2] = -1e30f;
                if (kv + 1 > row_lo + 8) S[nf][3] = -1e30f;
            }
        }

        // row max (rows r and r+8)
        float rm0 = -1e30f, rm1 = -1e30f;
#pragma unroll
        for (int nf = 0; nf < 8; nf++) {
            rm0 = fmaxf(rm0, fmaxf(S[nf][0], S[nf][1]));
            rm1 = fmaxf(rm1, fmaxf(S[nf][2], S[nf][3]));
        }
        rm0 = fmaxf(rm0, __shfl_xor_sync(0xffffffffu, rm0, 1));
        rm0 = fmaxf(rm0, __shfl_xor_sync(0xffffffffu, rm0, 2));
        rm1 = fmaxf(rm1, __shfl_xor_sync(0xffffffffu, rm1, 1));
        rm1 = fmaxf(rm1, __shfl_xor_sync(0xffffffffu, rm1, 2));

        const float mn0 = fmaxf(m0r, rm0);
        const float mn1 = fmaxf(m1r, rm1);
        const float cr0 = ex2(m0r - mn0);
        const float cr1 = ex2(m1r - mn1);
        m0r = mn0; m1r = mn1;

        // P = exp2(S - m); row sums
        float rs0 = 0.f, rs1 = 0.f;
#pragma unroll
        for (int nf = 0; nf < 8; nf++) {
            S[nf][0] = ex2(S[nf][0] - mn0);
            S[nf][1] = ex2(S[nf][1] - mn0);
            S[nf][2] = ex2(S[nf][2] - mn1);
            S[nf][3] = ex2(S[nf][3] - mn1);
            rs0 += S[nf][0] + S[nf][1];
            rs1 += S[nf][2] + S[nf][3];
        }
        rs0 += __shfl_xor_sync(0xffffffffu, rs0, 1);
        rs0 += __shfl_xor_sync(0xffffffffu, rs0, 2);
        rs1 += __shfl_xor_sync(0xffffffffu, rs1, 1);
        rs1 += __shfl_xor_sync(0xffffffffu, rs1, 2);
        l0r = l0r * cr0 + rs0;
        l1r = l1r * cr1 + rs1;

        // rescale O
#pragma unroll
        for (int nf = 0; nf < 8; nf++) {
            O[nf][0] *= cr0; O[nf][1] *= cr0;
            O[nf][2] *= cr1; O[nf][3] *= cr1;
        }

        // ---- O += P V (per kv-group kf) ----
#pragma unroll
        for (int kf = 0; kf < 4; kf++) {
            // P A-frags (hi + residual lo) straight from S regs
            uint32_t pah[4], pal[4];
#pragma unroll
            for (int half = 0; half < 2; half++) {
                float p0 = S[2 * kf + half][0], p1 = S[2 * kf + half][1];
                float p2 = S[2 * kf + half][2], p3 = S[2 * kf + half][3];
                __nv_bfloat16 h0 = __float2bfloat16(p0);
                __nv_bfloat16 h1 = __float2bfloat16(p1);
                __nv_bfloat16 h2 = __float2bfloat16(p2);
                __nv_bfloat16 h3 = __float2bfloat16(p3);
                __nv_bfloat162 t01(h0, h1), t23(h2, h3);
                pah[2 * half + 0] = *reinterpret_cast<uint32_t*>(&t01);
                pah[2 * half + 1] = *reinterpret_cast<uint32_t*>(&t23);
                pal[2 * half + 0] = packbf2(p0 - __bfloat162float(h0),
                                            p1 - __bfloat162float(h1));
                pal[2 * half + 1] = packbf2(p2 - __bfloat162float(h2),
                                            p3 - __bfloat162float(h3));
            }
            // wait: A frag order is {a0,a1,a2,a3} = {nf even c01, nf even c23,
            // nf odd c01, nf odd c23}; half-loop above builds exactly that.
            uint32_t vh[8][2], vl[8][2];
#pragma unroll
            for (int bi = 0; bi < 4; bi++) {
                uint32_t vrow = kf * 16 + (quad & 1) * 8 + qr;
                uint32_t vcb = bi * 32 + (quad >> 1) * 16;
                uint32_t o = swz(vrow, vcb);
                ldmx4t(vh[bi * 2][0], vh[bi * 2][1], vh[bi * 2 + 1][0],
                       vh[bi * 2 + 1][1], tVh + o);
                ldmx4t(vl[bi * 2][0], vl[bi * 2][1], vl[bi * 2 + 1][0],
                       vl[bi * 2 + 1][1], tVl + o);
            }
#pragma unroll
            for (int nf = 0; nf < 8; nf++) {
                mma16816(O[nf][0], O[nf][1], O[nf][2], O[nf][3],
                         pah[0], pah[1], pah[2], pah[3], vh[nf][0], vh[nf][1]);
                mma16816(O[nf][0], O[nf][1], O[nf][2], O[nf][3],
                         pah[0], pah[1], pah[2], pah[3], vl[nf][0], vl[nf][1]);
                mma16816(O[nf][0], O[nf][1], O[nf][2], O[nf][3],
                         pal[0], pal[1], pal[2], pal[3], vh[nf][0], vh[nf][1]);
            }
        }
        __syncthreads();
    }

    // ---- epilogue: normalize, split, store ----
    const float li0 = 1.f / l0r;
    const float li1 = 1.f / l1r;
    const size_t r0 = (size_t)(b * T_) + row_lo;
    const int colb = h * D_ + 2 * (lane & 3);
#pragma unroll
    for (int nf = 0; nf < 8; nf++) {
        float o0 = O[nf][0] * li0, o1 = O[nf][1] * li0;
        float o2 = O[nf][2] * li1, o3 = O[nf][3] * li1;
        const size_t c = colb + nf * 8;
        __nv_bfloat16 h0 = __float2bfloat16(o0);
        __nv_bfloat16 h1 = __float2bfloat16(o1);
        __nv_bfloat16 h2 = __float2bfloat16(o2);
        __nv_bfloat16 h3 = __float2bfloat16(o3);
        *reinterpret_cast<__nv_bfloat162*>(yh + r0 * C_ + c) = __nv_bfloat162(h0, h1);
        *reinterpret_cast<__nv_bfloat162*>(yh + (r0 + 8) * C_ + c) = __nv_bfloat162(h2, h3);
        *reinterpret_cast<__nv_bfloat162*>(yl + r0 * C_ + c) =
            __nv_bfloat162(__float2bfloat16(o0 - __bfloat162float(h0)),
                           __float2bfloat16(o1 - __bfloat162float(h1)));
        *reinterpret_cast<__nv_bfloat162*>(yl + (r0 + 8) * C_ + c) =
            __nv_bfloat162(__float2bfloat16(o2 - __bfloat162float(h2)),
                           __float2bfloat16(o3 - __bfloat162float(h3)));
    }
}

// ---------------- launch ----------------
extern "C" void kernel_launch(void* const* d_in, const int* in_sizes, int n_in,
                              void* d_out, int out_size)
{
    const float* x      = (const float*)d_in[0];
    const float* w_attn = (const float*)d_in[1];
    const float* w_proj = (const float*)d_in[2];
    float* out = (float*)d_out;

    __nv_bfloat16 *xhi, *xlo, *wahi, *walo, *wphi, *wplo, *qkvh, *qkvl, *yhi, *ylo;
    cudaGetSymbolAddress((void**)&xhi, g_xhi);
    cudaGetSymbolAddress((void**)&xlo, g_xlo);
    cudaGetSymbolAddress((void**)&wahi, g_wahi);
    cudaGetSymbolAddress((void**)&walo, g_walo);
    cudaGetSymbolAddress((void**)&wphi, g_wphi);
    cudaGetSymbolAddress((void**)&wplo, g_wplo);
    cudaGetSymbolAddress((void**)&qkvh, g_qkvh);
    cudaGetSymbolAddress((void**)&qkvl, g_qkvl);
    cudaGetSymbolAddress((void**)&yhi, g_yhi);
    cudaGetSymbolAddress((void**)&ylo, g_ylo);

    cudaFuncSetAttribute(gemm_mma, cudaFuncAttributeMaxDynamicSharedMemorySize, SMEM_TOTAL);
    cudaFuncSetAttribute(flash_attn_mma, cudaFuncAttributeMaxDynamicSharedMemorySize, AT_SMEM);

    {
        int n4 = M_ROWS * C_ / 4;
        split_bf16<<<(n4 + 255) / 256, 256>>>((const float4*)x,
            (__nv_bfloat162*)xhi, (__nv_bfloat162*)xlo, n4);
    }
    {
        int n4 = C3_ * C_ / 4;
        split_bf16<<<(n4 + 255) / 256, 256>>>((const float4*)w_attn,
            (__nv_bfloat162*)wahi, (__nv_bfloat162*)walo, n4);
    }
    {
        int n4 = C_ * C_ / 4;
        split_bf16<<<(n4 + 255) / 256, 256>>>((const float4*)w_proj,
            (__nv_bfloat162*)wphi, (__nv_bfloat162*)wplo, n4);
    }

    // 1) QKV: write bf16 hi/lo directly
    {
        dim3 g(C3_ / 128, M_ROWS / 128);
        gemm_mma<<<g, 256, SMEM_TOTAL>>>(xhi, xlo, wahi, walo,
                                         nullptr, qkvh, qkvl, 1, M_ROWS, C3_, C_);
    }
    // 2) tensor-core flash attention
    {
        dim3 g(T_ / 128, H_, B_);
        flash_attn_mma<<<g, 256, AT_SMEM>>>(qkvh, qkvl, yhi, ylo);
    }
    // 3) out = y @ w_proj^T (fp32 out)
    {
        dim3 g(C_ / 128, M_ROWS / 128);
        gemm_mma<<<g, 256, SMEM_TOTAL>>>(yhi, ylo, wphi, wplo,
                                         out, nullptr, nullptr, 0, M_ROWS, C_, C_);
    }
}

// round 11
// speedup vs baseline: 4.5686x; 1.1512x over previous
#include <cuda_runtime.h>
#include <cuda_fp16.h>
#include <cstdint>

#define B_ 4
#define T_ 2048
#define C_ 1024
#define H_ 16
#define D_ 64
#define C3_ 3072
#define M_ROWS (B_ * T_)

// ---------------- scratch (device globals: allocation-free) ----------------
__device__ __half g_xhi[(size_t)M_ROWS * C_];
__device__ __half g_wahi[(size_t)C3_ * C_];
__device__ __half g_walo[(size_t)C3_ * C_];
__device__ __half g_wphi[(size_t)C_ * C_];
__device__ __half g_wplo[(size_t)C_ * C_];
__device__ __half g_qkvh[(size_t)M_ROWS * C3_];
__device__ __half g_qkvl[(size_t)M_ROWS * C3_];
__device__ __half g_yhi[(size_t)M_ROWS * C_];
__device__ __half g_ylo[(size_t)M_ROWS * C_];

// ---------------- helpers ----------------
__device__ __forceinline__ uint32_t smem_u32(const void* p) {
    uint32_t a;
    asm("{ .reg .u64 t; cvta.to.shared.u64 t, %1; cvt.u32.u64 %0, t; }"
        : "=r"(a) : "l"(p));
    return a;
}
__device__ __forceinline__ void cp_async16(uint32_t dst, const void* src) {
    asm volatile("cp.async.cg.shared.global [%0], [%1], 16;" :: "r"(dst), "l"(src));
}
__device__ __forceinline__ void cp_commit() {
    asm volatile("cp.async.commit_group;" ::: "memory");
}
__device__ __forceinline__ void cp_wait2() {
    asm volatile("cp.async.wait_group 2;" ::: "memory");
}
__device__ __forceinline__ void ldmx4(uint32_t& r0, uint32_t& r1, uint32_t& r2,
                                      uint32_t& r3, uint32_t addr) {
    asm volatile("ldmatrix.sync.aligned.m8n8.x4.shared.b16 {%0,%1,%2,%3}, [%4];"
                 : "=r"(r0), "=r"(r1), "=r"(r2), "=r"(r3) : "r"(addr));
}
__device__ __forceinline__ void ldmx4t(uint32_t& r0, uint32_t& r1, uint32_t& r2,
                                       uint32_t& r3, uint32_t addr) {
    asm volatile("ldmatrix.sync.aligned.m8n8.x4.trans.shared.b16 {%0,%1,%2,%3}, [%4];"
                 : "=r"(r0), "=r"(r1), "=r"(r2), "=r"(r3) : "r"(addr));
}
__device__ __forceinline__ void mma16816(float& d0, float& d1, float& d2, float& d3,
                                         uint32_t a0, uint32_t a1, uint32_t a2, uint32_t a3,
                                         uint32_t b0, uint32_t b1) {
    asm volatile("mma.sync.aligned.m16n8k16.row.col.f32.f16.f16.f32 "
                 "{%0,%1,%2,%3}, {%4,%5,%6,%7}, {%8,%9}, {%0,%1,%2,%3};"
                 : "+f"(d0), "+f"(d1), "+f"(d2), "+f"(d3)
                 : "r"(a0), "r"(a1), "r"(a2), "r"(a3), "r"(b0), "r"(b1));
}
__device__ __forceinline__ float ex2(float x) {
    float y;
    asm("ex2.approx.ftz.f32 %0, %1;" : "=f"(y) : "f"(x));
    return y;
}
__device__ __forceinline__ uint32_t packh2(float a, float b) {
    __half2 t = __floats2half2_rn(a, b);   // .x = a
    return *reinterpret_cast<uint32_t*>(&t);
}
// swizzled byte offset: row-major 128B rows, xor bits 4-6 by row&7
__device__ __forceinline__ uint32_t swz(uint32_t row, uint32_t kb) {
    return row * 128u + (kb ^ ((row & 7u) * 16u));
}

// ---------------- fp32 -> fp16 (hi only / hi+lo) ----------------
__global__ __launch_bounds__(256)
void trunc_f16(const float4* __restrict__ in, __half2* __restrict__ hi, int n4)
{
    int i = blockIdx.x * 256 + threadIdx.x;
    if (i >= n4) return;
    float4 v = in[i];
    hi[2 * i + 0] = __floats2half2_rn(v.x, v.y);
    hi[2 * i + 1] = __floats2half2_rn(v.z, v.w);
}

__global__ __launch_bounds__(256)
void split_f16(const float4* __restrict__ in, __half2* __restrict__ hi,
               __half2* __restrict__ lo, int n4)
{
    int i = blockIdx.x * 256 + threadIdx.x;
    if (i >= n4) return;
    float4 v = in[i];
    __half h0 = __float2half_rn(v.x);
    __half h1 = __float2half_rn(v.y);
    __half h2 = __float2half_rn(v.z);
    __half h3 = __float2half_rn(v.w);
    hi[2 * i + 0] = __halves2half2(h0, h1);
    hi[2 * i + 1] = __halves2half2(h2, h3);
    lo[2 * i + 0] = __floats2half2_rn(v.x - __half2float(h0), v.y - __half2float(h1));
    lo[2 * i + 1] = __floats2half2_rn(v.z - __half2float(h2), v.w - __half2float(h3));
}

// ---------------- mma.sync GEMM: C = A @ W^T (fp16 split, 3-stage) ---------
// TERMS=2: Ah*Bh + Ah*Bl (skips Alo entirely)
// TERMS=3: + Al*Bh
#define TILE_B 16384
#define STAGE_B (4 * TILE_B)
#define GEMM_SMEM (3 * STAGE_B)

template<int TERMS>
__global__ __launch_bounds__(256, 1)
void gemm_mma(const __half* __restrict__ Ahi, const __half* __restrict__ Alo,
              const __half* __restrict__ Bhi, const __half* __restrict__ Blo,
              float* __restrict__ Cout, __half* __restrict__ Chi,
              __half* __restrict__ Clo, int split_out, int M, int N, int K)
{
    extern __shared__ char smem[];
    const uint32_t sbase = smem_u32(smem);
    const int tid = threadIdx.x;
    const int wid = tid >> 5;
    const int lane = tid & 31;
    const int wm = wid & 1;
    const int wn = wid >> 1;
    const size_t m0 = (size_t)blockIdx.y * 128;
    const size_t n0 = (size_t)blockIdx.x * 128;
    const int quad = lane >> 3;
    const int qr = lane & 7;

    float acc[4][4][4];
#pragma unroll
    for (int i = 0; i < 4; i++)
#pragma unroll
        for (int j = 0; j < 4; j++)
#pragma unroll
            for (int r = 0; r < 4; r++) acc[i][j][r] = 0.f;

    const int NCH = K >> 6;

    auto issue_chunk = [&](int ch, int stage) {
        const int k0 = ch * 64;
        char* base = smem + stage * STAGE_B;
#pragma unroll
        for (int it = 0; it < 4; it++) {
            int idx = it * 256 + tid;
            uint32_t row = idx >> 3;
            uint32_t c16 = idx & 7;
            uint32_t off = swz(row, c16 * 16u);
            size_t akoff = (m0 + row) * (size_t)K + k0 + c16 * 8;
            size_t bkoff = (n0 + row) * (size_t)K + k0 + c16 * 8;
            cp_async16(smem_u32(base + 0 * TILE_B + off), Ahi + akoff);
            if (TERMS == 3)
                cp_async16(smem_u32(base + 1 * TILE_B + off), Alo + akoff);
            cp_async16(smem_u32(base + 2 * TILE_B + off), Bhi + bkoff);
            cp_async16(smem_u32(base + 3 * TILE_B + off), Blo + bkoff);
        }
        cp_commit();
    };

    issue_chunk(0, 0);
    issue_chunk(1, 1);

    for (int ch = 0; ch < NCH; ch++) {
        const int s = ch % 3;
        if (ch + 2 < NCH) issue_chunk(ch + 2, (ch + 2) % 3);
        else cp_commit();
        cp_wait2();          // chunk ch resident; ch+1, ch+2 still in flight
        __syncthreads();

        const uint32_t tAh = sbase + s * STAGE_B + 0 * TILE_B;
        const uint32_t tAl = sbase + s * STAGE_B + 1 * TILE_B;
        const uint32_t tBh = sbase + s * STAGE_B + 2 * TILE_B;
        const uint32_t tBl = sbase + s * STAGE_B + 3 * TILE_B;

#pragma unroll
        for (int kk = 0; kk < 4; kk++) {
            const uint32_t kb = kk * 32;
            uint32_t ah[4][4], al[4][4];
#pragma unroll
            for (int mi = 0; mi < 4; mi++) {
                uint32_t arow = wm * 64 + mi * 16 + (quad & 1) * 8 + qr;
                uint32_t akb = kb + (quad >> 1) * 16;
                uint32_t o = swz(arow, akb);
                ldmx4(ah[mi][0], ah[mi][1], ah[mi][2], ah[mi][3], tAh + o);
                if (TERMS == 3)
                    ldmx4(al[mi][0], al[mi][1], al[mi][2], al[mi][3], tAl + o);
            }
            uint32_t bh[4][2], bl[4][2];
#pragma unroll
            for (int bi = 0; bi < 2; bi++) {
                uint32_t brow = wn * 32 + bi * 16 + (quad >> 1) * 8 + qr;
                uint32_t bkb = kb + (quad & 1) * 16;
                uint32_t o = swz(brow, bkb);
                ldmx4(bh[bi * 2][0], bh[bi * 2][1], bh[bi * 2 + 1][0], bh[bi * 2 + 1][1],
                      tBh + o);
                ldmx4(bl[bi * 2][0], bl[bi * 2][1], bl[bi * 2 + 1][0], bl[bi * 2 + 1][1],
                      tBl + o);
            }
#pragma unroll
            for (int mi = 0; mi < 4; mi++) {
#pragma unroll
                for (int ni = 0; ni < 4; ni++) {
                    float* d = acc[mi][ni];
                    mma16816(d[0], d[1], d[2], d[3],
                             ah[mi][0], ah[mi][1], ah[mi][2], ah[mi][3],
                             bh[ni][0], bh[ni][1]);
                    mma16816(d[0], d[1], d[2], d[3],
                             ah[mi][0], ah[mi][1], ah[mi][2], ah[mi][3],
                             bl[ni][0], bl[ni][1]);
                    if (TERMS == 3)
                        mma16816(d[0], d[1], d[2], d[3],
                                 al[mi][0], al[mi][1], al[mi][2], al[mi][3],
                                 bh[ni][0], bh[ni][1]);
                }
            }
        }
        __syncthreads();   // protect stage s before it is re-issued (iter ch+1)
    }

    const int g = lane >> 2;
    const int ti = lane & 3;
#pragma unroll
    for (int mi = 0; mi < 4; mi++) {
#pragma unroll
        for (int ni = 0; ni < 4; ni++) {
            size_t row = m0 + wm * 64 + mi * 16 + g;
            size_t col = n0 + wn * 32 + ni * 8 + 2 * ti;
            float* a = acc[mi][ni];
            if (split_out) {
                __half h0 = __float2half_rn(a[0]);
                __half h1 = __float2half_rn(a[1]);
                __half h2 = __float2half_rn(a[2]);
                __half h3 = __float2half_rn(a[3]);
                *reinterpret_cast<__half2*>(Chi + row * N + col) = __halves2half2(h0, h1);
                *reinterpret_cast<__half2*>(Chi + (row + 8) * N + col) = __halves2half2(h2, h3);
                *reinterpret_cast<__half2*>(Clo + row * N + col) =
                    __floats2half2_rn(a[0] - __half2float(h0), a[1] - __half2float(h1));
                *reinterpret_cast<__half2*>(Clo + (row + 8) * N + col) =
                    __floats2half2_rn(a[2] - __half2float(h2), a[3] - __half2float(h3));
            } else {
                *reinterpret_cast<float2*>(Cout + row * N + col) =
                    make_float2(a[0], a[1]);
                *reinterpret_cast<float2*>(Cout + (row + 8) * N + col) =
                    make_float2(a[2], a[3]);
            }
        }
    }
}

// ---------------- tensor-core flash attention (causal, fp16 3-term) --------
// CTA: 128 q rows, 8 warps x 16 rows. KV tiles of 64, 3-stage cp.async.
// SMEM: Q (hi+lo) 32KB at offset 0, then 3 KV stages x 32KB.
#define AT_TILE 8192          // 64 rows x 128B
#define AT_STAGE (4 * AT_TILE)
#define AT_QB 32768
#define AT_SMEM (AT_QB + 3 * AT_STAGE)
#define SCALE_LOG2E 0.1803368801111204f   // (1/8) * log2(e)

__global__ __launch_bounds__(256, 1)
void flash_attn_mma(const __half* __restrict__ qh, const __half* __restrict__ ql,
                    __half* __restrict__ yh, __half* __restrict__ yl)
{
    extern __shared__ char smem[];
    const uint32_t sbase = smem_u32(smem);
    const int tid = threadIdx.x;
    const int wid = tid >> 5;
    const int lane = tid & 31;
    const int quad = lane >> 3;
    const int qr = lane & 7;
    const int b = blockIdx.z;
    const int h = blockIdx.y;
    const int qt = gridDim.x - 1 - blockIdx.x;
    const int q0 = qt * 128;
    const int nt = 2 * qt + 2;

    const size_t bbase = (size_t)(b * T_) * C3_;
    const __half* qsh = qh + bbase + h * D_;
    const __half* qsl = ql + bbase + h * D_;
    const __half* ksh = qh + bbase + C_ + h * D_;
    const __half* ksl = ql + bbase + C_ + h * D_;
    const __half* vsh = qh + bbase + 2 * C_ + h * D_;
    const __half* vsl = ql + bbase + 2 * C_ + h * D_;

    auto issue_kv = [&](int t, int stage) {
        const int j0 = t * 64;
#pragma unroll
        for (int it = 0; it < 8; it++) {
            const int tile = it >> 1;
            const uint32_t r = (it & 1) * 32 + (tid >> 3);
            const uint32_t c16 = tid & 7;
            const __half* src =
                (tile == 0 ? ksh : tile == 1 ? ksl : tile == 2 ? vsh : vsl)
                + (size_t)(j0 + r) * C3_ + c16 * 8;
            cp_async16(sbase + AT_QB + stage * AT_STAGE + tile * AT_TILE
                       + swz(r, c16 * 16u), src);
        }
        cp_commit();
    };

    // group 0: Q hi+lo
#pragma unroll
    for (int it = 0; it < 8; it++) {
        const int half = it >> 2;
        const uint32_t r = (it & 3) * 32 + (tid >> 3);
        const uint32_t c16 = tid & 7;
        const __half* src = (half == 0 ? qsh : qsl) + (size_t)(q0 + r) * C3_ + c16 * 8;
        cp_async16(sbase + half * 16384 + swz(r, c16 * 16u), src);
    }
    cp_commit();
    issue_kv(0, 0);   // group 1
    issue_kv(1, 1);   // group 2
    cp_wait2();       // Q resident
    __syncthreads();

    // Q fragments (Q region never rewritten)
    uint32_t Qh[4][4], Ql[4][4];
#pragma unroll
    for (int kf = 0; kf < 4; kf++) {
        uint32_t arow = wid * 16 + (quad & 1) * 8 + qr;
        uint32_t akb = kf * 32 + (quad >> 1) * 16;
        uint32_t o = swz(arow, akb);
        ldmx4(Qh[kf][0], Qh[kf][1], Qh[kf][2], Qh[kf][3], sbase + o);
        ldmx4(Ql[kf][0], Ql[kf][1], Ql[kf][2], Ql[kf][3], sbase + 16384 + o);
    }

    float O[8][4];
#pragma unroll
    for (int i = 0; i < 8; i++)
#pragma unroll
        for (int r = 0; r < 4; r++) O[i][r] = 0.f;
    float m0r = -1e30f, m1r = -1e30f, l0r = 0.f, l1r = 0.f;
    const int row_lo = q0 + wid * 16 + (lane >> 2);

    for (int t = 0; t < nt; t++) {
        const int s = t % 3;
        if (t + 2 < nt) issue_kv(t + 2, (t + 2) % 3);
        else cp_commit();
        cp_wait2();
        __syncthreads();

        const int j0 = t * 64;
        const uint32_t stage = sbase + AT_QB + s * AT_STAGE;
        const uint32_t tKh = stage + 0 * AT_TILE;
        const uint32_t tKl = stage + 1 * AT_TILE;
        const uint32_t tVh = stage + 2 * AT_TILE;
        const uint32_t tVl = stage + 3 * AT_TILE;

        // ---- S = Q K^T (3-term) ----
        float S[8][4];
#pragma unroll
        for (int i = 0; i < 8; i++)
#pragma unroll
            for (int r = 0; r < 4; r++) S[i][r] = 0.f;

#pragma unroll
        for (int kf = 0; kf < 4; kf++) {
            uint32_t bh[8][2], bl[8][2];
#pragma unroll
            for (int bi = 0; bi < 4; bi++) {
                uint32_t brow = bi * 16 + (quad >> 1) * 8 + qr;
                uint32_t bkb = kf * 32 + (quad & 1) * 16;
                uint32_t o = swz(brow, bkb);
                ldmx4(bh[bi * 2][0], bh[bi * 2][1], bh[bi * 2 + 1][0], bh[bi * 2 + 1][1],
                      tKh + o);
                ldmx4(bl[bi * 2][0], bl[bi * 2][1], bl[bi * 2 + 1][0], bl[bi * 2 + 1][1],
                      tKl + o);
            }
#pragma unroll
            for (int nf = 0; nf < 8; nf++) {
                mma16816(S[nf][0], S[nf][1], S[nf][2], S[nf][3],
                         Qh[kf][0], Qh[kf][1], Qh[kf][2], Qh[kf][3],
                         bh[nf][0], bh[nf][1]);
                mma16816(S[nf][0], S[nf][1], S[nf][2], S[nf][3],
                         Qh[kf][0], Qh[kf][1], Qh[kf][2], Qh[kf][3],
                         bl[nf][0], bl[nf][1]);
                mma16816(S[nf][0], S[nf][1], S[nf][2], S[nf][3],
                         Ql[kf][0], Ql[kf][1], Ql[kf][2], Ql[kf][3],
                         bh[nf][0], bh[nf][1]);
            }
        }

        // scale + causal mask
#pragma unroll
        for (int nf = 0; nf < 8; nf++)
#pragma unroll
            for (int r = 0; r < 4; r++) S[nf][r] *= SCALE_LOG2E;

        if (j0 + 63 > q0 + wid * 16) {
            const int kvb = j0 + 2 * (lane & 3);
#pragma unroll
            for (int nf = 0; nf < 8; nf++) {
                const int kv = kvb + nf * 8;
                if (kv     > row_lo)     S[nf][0] = -1e30f;
                if (kv + 1 > row_lo)     S[nf][1] = -1e30f;
                if (kv     > row_lo + 8) S[nf][2] = -1e30f;
                if (kv + 1 > row_lo + 8) S[nf][3] = -1e30f;
            }
        }

        // row max
        float rm0 = -1e30f, rm1 = -1e30f;
#pragma unroll
        for (int nf = 0; nf < 8; nf++) {
            rm0 = fmaxf(rm0, fmaxf(S[nf][0], S[nf][1]));
            rm1 = fmaxf(rm1, fmaxf(S[nf][2], S[nf][3]));
        }
        rm0 = fmaxf(rm0, __shfl_xor_sync(0xffffffffu, rm0, 1));
        rm0 = fmaxf(rm0, __shfl_xor_sync(0xffffffffu, rm0, 2));
        rm1 = fmaxf(rm1, __shfl_xor_sync(0xffffffffu, rm1, 1));
        rm1 = fmaxf(rm1, __shfl_xor_sync(0xffffffffu, rm1, 2));

        const float mn0 = fmaxf(m0r, rm0);
        const float mn1 = fmaxf(m1r, rm1);
        const float cr0 = ex2(m0r - mn0);
        const float cr1 = ex2(m1r - mn1);
        m0r = mn0; m1r = mn1;

        float rs0 = 0.f, rs1 = 0.f;
#pragma unroll
        for (int nf = 0; nf < 8; nf++) {
            S[nf][0] = ex2(S[nf][0] - mn0);
            S[nf][1] = ex2(S[nf][1] - mn0);
            S[nf][2] = ex2(S[nf][2] - mn1);
            S[nf][3] = ex2(S[nf][3] - mn1);
            rs0 += S[nf][0] + S[nf][1];
            rs1 += S[nf][2] + S[nf][3];
        }
        rs0 += __shfl_xor_sync(0xffffffffu, rs0, 1);
        rs0 += __shfl_xor_sync(0xffffffffu, rs0, 2);
        rs1 += __shfl_xor_sync(0xffffffffu, rs1, 1);
        rs1 += __shfl_xor_sync(0xffffffffu, rs1, 2);
        l0r = l0r * cr0 + rs0;
        l1r = l1r * cr1 + rs1;

#pragma unroll
        for (int nf = 0; nf < 8; nf++) {
            O[nf][0] *= cr0; O[nf][1] *= cr0;
            O[nf][2] *= cr1; O[nf][3] *= cr1;
        }

        // ---- O += P V (3-term) ----
#pragma unroll
        for (int kf = 0; kf < 4; kf++) {
            uint32_t pah[4], pal[4];
#pragma unroll
            for (int half = 0; half < 2; half++) {
                float p0 = S[2 * kf + half][0], p1 = S[2 * kf + half][1];
                float p2 = S[2 * kf + half][2], p3 = S[2 * kf + half][3];
                __half h0 = __float2half_rn(p0);
                __half h1 = __float2half_rn(p1);
                __half h2 = __float2half_rn(p2);
                __half h3 = __float2half_rn(p3);
                __half2 t01 = __halves2half2(h0, h1);
                __half2 t23 = __halves2half2(h2, h3);
                pah[2 * half + 0] = *reinterpret_cast<uint32_t*>(&t01);
                pah[2 * half + 1] = *reinterpret_cast<uint32_t*>(&t23);
                pal[2 * half + 0] = packh2(p0 - __half2float(h0), p1 - __half2float(h1));
                pal[2 * half + 1] = packh2(p2 - __half2float(h2), p3 - __half2float(h3));
            }
            uint32_t vh[8][2], vl[8][2];
#pragma unroll
            for (int bi = 0; bi < 4; bi++) {
                uint32_t vrow = kf * 16 + (quad & 1) * 8 + qr;
                uint32_t vcb = bi * 32 + (quad >> 1) * 16;
                uint32_t o = swz(vrow, vcb);
                ldmx4t(vh[bi * 2][0], vh[bi * 2][1], vh[bi * 2 + 1][0],
                       vh[bi * 2 + 1][1], tVh + o);
                ldmx4t(vl[bi * 2][0], vl[bi * 2][1], vl[bi * 2 + 1][0],
                       vl[bi * 2 + 1][1], tVl + o);
            }
#pragma unroll
            for (int nf = 0; nf < 8; nf++) {
                mma16816(O[nf][0], O[nf][1], O[nf][2], O[nf][3],
                         pah[0], pah[1], pah[2], pah[3], vh[nf][0], vh[nf][1]);
                mma16816(O[nf][0], O[nf][1], O[nf][2], O[nf][3],
                         pah[0], pah[1], pah[2], pah[3], vl[nf][0], vl[nf][1]);
                mma16816(O[nf][0], O[nf][1], O[nf][2], O[nf][3],
                         pal[0], pal[1], pal[2], pal[3], vh[nf][0], vh[nf][1]);
            }
        }
        __syncthreads();   // protect stage s before re-issue
    }

    // ---- epilogue: normalize, split, store ----
    const float li0 = 1.f / l0r;
    const float li1 = 1.f / l1r;
    const size_t r0 = (size_t)(b * T_) + row_lo;
    const int colb = h * D_ + 2 * (lane & 3);
#pragma unroll
    for (int nf = 0; nf < 8; nf++) {
        float o0 = O[nf][0] * li0, o1 = O[nf][1] * li0;
        float o2 = O[nf][2] * li1, o3 = O[nf][3] * li1;
        const size_t c = colb + nf * 8;
        __half h0 = __float2half_rn(o0);
        __half h1 = __float2half_rn(o1);
        __half h2 = __float2half_rn(o2);
        __half h3 = __float2half_rn(o3);
        *reinterpret_cast<__half2*>(yh + r0 * C_ + c) = __halves2half2(h0, h1);
        *reinterpret_cast<__half2*>(yh + (r0 + 8) * C_ + c) = __halves2half2(h2, h3);
        *reinterpret_cast<__half2*>(yl + r0 * C_ + c) =
            __floats2half2_rn(o0 - __half2float(h0), o1 - __half2float(h1));
        *reinterpret_cast<__half2*>(yl + (r0 + 8) * C_ + c) =
            __floats2half2_rn(o2 - __half2float(h2), o3 - __half2float(h3));
    }
}

// ---------------- launch ----------------
extern "C" void kernel_launch(void* const* d_in, const int* in_sizes, int n_in,
                              void* d_out, int out_size)
{
    const float* x      = (const float*)d_in[0];
    const float* w_attn = (const float*)d_in[1];
    const float* w_proj = (const float*)d_in[2];
    float* out = (float*)d_out;

    __half *xhi, *wahi, *walo, *wphi, *wplo, *qkvh, *qkvl, *yhi, *ylo;
    cudaGetSymbolAddress((void**)&xhi, g_xhi);
    cudaGetSymbolAddress((void**)&wahi, g_wahi);
    cudaGetSymbolAddress((void**)&walo, g_walo);
    cudaGetSymbolAddress((void**)&wphi, g_wphi);
    cudaGetSymbolAddress((void**)&wplo, g_wplo);
    cudaGetSymbolAddress((void**)&qkvh, g_qkvh);
    cudaGetSymbolAddress((void**)&qkvl, g_qkvl);
    cudaGetSymbolAddress((void**)&yhi, g_yhi);
    cudaGetSymbolAddress((void**)&ylo, g_ylo);

    cudaFuncSetAttribute(gemm_mma<2>, cudaFuncAttributeMaxDynamicSharedMemorySize, GEMM_SMEM);
    cudaFuncSetAttribute(gemm_mma<3>, cudaFuncAttributeMaxDynamicSharedMemorySize, GEMM_SMEM);
    cudaFuncSetAttribute(flash_attn_mma, cudaFuncAttributeMaxDynamicSharedMemorySize, AT_SMEM);

    {
        int n4 = M_ROWS * C_ / 4;
        trunc_f16<<<(n4 + 255) / 256, 256>>>((const float4*)x, (__half2*)xhi, n4);
    }
    {
        int n4 = C3_ * C_ / 4;
        split_f16<<<(n4 + 255) / 256, 256>>>((const float4*)w_attn,
            (__half2*)wahi, (__half2*)walo, n4);
    }
    {
        int n4 = C_ * C_ / 4;
        split_f16<<<(n4 + 255) / 256, 256>>>((const float4*)w_proj,
            (__half2*)wphi, (__half2*)wplo, n4);
    }

    // 1) QKV (2-term fp16): write fp16 hi/lo
    {
        dim3 g(C3_ / 128, M_ROWS / 128);
        gemm_mma<2><<<g, 256, GEMM_SMEM>>>(xhi, nullptr, wahi, walo,
                                           nullptr, qkvh, qkvl, 1, M_ROWS, C3_, C_);
    }
    // 2) tensor-core flash attention (3-term fp16)
    {
        dim3 g(T_ / 128, H_, B_);
        flash_attn_mma<<<g, 256, AT_SMEM>>>(qkvh, qkvl, yhi, ylo);
    }
    // 3) out = y @ w_proj^T (3-term fp16, fp32 out)
    {
        dim3 g(C_ / 128, M_ROWS / 128);
        gemm_mma<3><<<g, 256, GEMM_SMEM>>>(yhi, ylo, wphi, wplo,
                                           out, nullptr, nullptr, 0, M_ROWS, C_, C_);
    }
}

// round 12
// speedup vs baseline: 4.9557x; 1.0847x over previous
#include <cuda_runtime.h>
#include <cuda_fp16.h>
#include <cstdint>

#define B_ 4
#define T_ 2048
#define C_ 1024
#define H_ 16
#define D_ 64
#define C3_ 3072
#define M_ROWS (B_ * T_)

// ---------------- scratch (device globals: allocation-free) ----------------
__device__ __half g_xhi[(size_t)M_ROWS * C_];
__device__ __half g_wahi[(size_t)C3_ * C_];
__device__ __half g_walo[(size_t)C3_ * C_];
__device__ __half g_wphi[(size_t)C_ * C_];
__device__ __half g_wplo[(size_t)C_ * C_];
__device__ __half g_qkvh[(size_t)M_ROWS * C3_];
__device__ __half g_qkvl[(size_t)M_ROWS * C3_];
__device__ __half g_yhi[(size_t)M_ROWS * C_];

// ---------------- helpers ----------------
__device__ __forceinline__ uint32_t smem_u32(const void* p) {
    uint32_t a;
    asm("{ .reg .u64 t; cvta.to.shared.u64 t, %1; cvt.u32.u64 %0, t; }"
        : "=r"(a) : "l"(p));
    return a;
}
__device__ __forceinline__ void cp_async16(uint32_t dst, const void* src) {
    asm volatile("cp.async.cg.shared.global [%0], [%1], 16;" :: "r"(dst), "l"(src));
}
__device__ __forceinline__ void cp_commit() {
    asm volatile("cp.async.commit_group;" ::: "memory");
}
__device__ __forceinline__ void cp_wait2() {
    asm volatile("cp.async.wait_group 2;" ::: "memory");
}
__device__ __forceinline__ void cp_wait3() {
    asm volatile("cp.async.wait_group 3;" ::: "memory");
}
__device__ __forceinline__ void ldmx4(uint32_t& r0, uint32_t& r1, uint32_t& r2,
                                      uint32_t& r3, uint32_t addr) {
    asm volatile("ldmatrix.sync.aligned.m8n8.x4.shared.b16 {%0,%1,%2,%3}, [%4];"
                 : "=r"(r0), "=r"(r1), "=r"(r2), "=r"(r3) : "r"(addr));
}
__device__ __forceinline__ void ldmx4t(uint32_t& r0, uint32_t& r1, uint32_t& r2,
                                       uint32_t& r3, uint32_t addr) {
    asm volatile("ldmatrix.sync.aligned.m8n8.x4.trans.shared.b16 {%0,%1,%2,%3}, [%4];"
                 : "=r"(r0), "=r"(r1), "=r"(r2), "=r"(r3) : "r"(addr));
}
__device__ __forceinline__ void mma16816(float& d0, float& d1, float& d2, float& d3,
                                         uint32_t a0, uint32_t a1, uint32_t a2, uint32_t a3,
                                         uint32_t b0, uint32_t b1) {
    asm volatile("mma.sync.aligned.m16n8k16.row.col.f32.f16.f16.f32 "
                 "{%0,%1,%2,%3}, {%4,%5,%6,%7}, {%8,%9}, {%0,%1,%2,%3};"
                 : "+f"(d0), "+f"(d1), "+f"(d2), "+f"(d3)
                 : "r"(a0), "r"(a1), "r"(a2), "r"(a3), "r"(b0), "r"(b1));
}
__device__ __forceinline__ float ex2(float x) {
    float y;
    asm("ex2.approx.ftz.f32 %0, %1;" : "=f"(y) : "f"(x));
    return y;
}
__device__ __forceinline__ uint32_t packh2(float a, float b) {
    __half2 t = __floats2half2_rn(a, b);   // .x = a
    return *reinterpret_cast<uint32_t*>(&t);
}
// swizzled byte offset: row-major 128B rows, xor bits 4-6 by row&7
__device__ __forceinline__ uint32_t swz(uint32_t row, uint32_t kb) {
    return row * 128u + (kb ^ ((row & 7u) * 16u));
}

// ---------------- fp32 -> fp16 (hi only / hi+lo) ----------------
__global__ __launch_bounds__(256)
void trunc_f16(const float4* __restrict__ in, __half2* __restrict__ hi, int n4)
{
    int i = blockIdx.x * 256 + threadIdx.x;
    if (i >= n4) return;
    float4 v = in[i];
    hi[2 * i + 0] = __floats2half2_rn(v.x, v.y);
    hi[2 * i + 1] = __floats2half2_rn(v.z, v.w);
}

__global__ __launch_bounds__(256)
void split_f16(const float4* __restrict__ in, __half2* __restrict__ hi,
               __half2* __restrict__ lo, int n4)
{
    int i = blockIdx.x * 256 + threadIdx.x;
    if (i >= n4) return;
    float4 v = in[i];
    __half h0 = __float2half_rn(v.x);
    __half h1 = __float2half_rn(v.y);
    __half h2 = __float2half_rn(v.z);
    __half h3 = __float2half_rn(v.w);
    hi[2 * i + 0] = __halves2half2(h0, h1);
    hi[2 * i + 1] = __halves2half2(h2, h3);
    lo[2 * i + 0] = __floats2half2_rn(v.x - __half2float(h0), v.y - __half2float(h1));
    lo[2 * i + 1] = __floats2half2_rn(v.z - __half2float(h2), v.w - __half2float(h3));
}

// ---------------- mma.sync GEMM: C = A @ W^T (2-term fp16, 4-stage) --------
// C = Ah*(Wh + Wl). Stage = {Ah, Bh, Bl} = 48KB; 4 stages, 1 barrier/chunk.
#define TILE_B 16384
#define STAGE_B (3 * TILE_B)
#define GEMM_SMEM (4 * STAGE_B)

__global__ __launch_bounds__(256, 1)
void gemm_mma(const __half* __restrict__ Ahi,
              const __half* __restrict__ Bhi, const __half* __restrict__ Blo,
              float* __restrict__ Cout, __half* __restrict__ Chi,
              __half* __restrict__ Clo, int split_out, int M, int N, int K)
{
    extern __shared__ char smem[];
    const uint32_t sbase = smem_u32(smem);
    const int tid = threadIdx.x;
    const int wid = tid >> 5;
    const int lane = tid & 31;
    const int wm = wid & 1;
    const int wn = wid >> 1;
    const size_t m0 = (size_t)blockIdx.y * 128;
    const size_t n0 = (size_t)blockIdx.x * 128;
    const int quad = lane >> 3;
    const int qr = lane & 7;

    float acc[4][4][4];
#pragma unroll
    for (int i = 0; i < 4; i++)
#pragma unroll
        for (int j = 0; j < 4; j++)
#pragma unroll
            for (int r = 0; r < 4; r++) acc[i][j][r] = 0.f;

    const int NCH = K >> 6;

    auto issue_chunk = [&](int ch, int stage) {
        const int k0 = ch * 64;
        char* base = smem + stage * STAGE_B;
#pragma unroll
        for (int it = 0; it < 4; it++) {
            int idx = it * 256 + tid;
            uint32_t row = idx >> 3;
            uint32_t c16 = idx & 7;
            uint32_t off = swz(row, c16 * 16u);
            size_t akoff = (m0 + row) * (size_t)K + k0 + c16 * 8;
            size_t bkoff = (n0 + row) * (size_t)K + k0 + c16 * 8;
            cp_async16(smem_u32(base + 0 * TILE_B + off), Ahi + akoff);
            cp_async16(smem_u32(base + 1 * TILE_B + off), Bhi + bkoff);
            cp_async16(smem_u32(base + 2 * TILE_B + off), Blo + bkoff);
        }
        cp_commit();
    };

    issue_chunk(0, 0);
    issue_chunk(1, 1);
    issue_chunk(2, 2);

    for (int ch = 0; ch < NCH; ch++) {
        const int s = ch & 3;
        cp_wait2();            // chunk ch resident (2 newest groups may pend)
        __syncthreads();       // publish stage s; retire stage (ch+3)&3
        if (ch + 3 < NCH) issue_chunk(ch + 3, (ch + 3) & 3);
        else cp_commit();      // keep group accounting uniform

        const uint32_t tAh = sbase + s * STAGE_B + 0 * TILE_B;
        const uint32_t tBh = sbase + s * STAGE_B + 1 * TILE_B;
        const uint32_t tBl = sbase + s * STAGE_B + 2 * TILE_B;

#pragma unroll
        for (int kk = 0; kk < 4; kk++) {
            const uint32_t kb = kk * 32;
            uint32_t ah[4][4];
#pragma unroll
            for (int mi = 0; mi < 4; mi++) {
                uint32_t arow = wm * 64 + mi * 16 + (quad & 1) * 8 + qr;
                uint32_t akb = kb + (quad >> 1) * 16;
                uint32_t o = swz(arow, akb);
                ldmx4(ah[mi][0], ah[mi][1], ah[mi][2], ah[mi][3], tAh + o);
            }
            uint32_t bh[4][2], bl[4][2];
#pragma unroll
            for (int bi = 0; bi < 2; bi++) {
                uint32_t brow = wn * 32 + bi * 16 + (quad >> 1) * 8 + qr;
                uint32_t bkb = kb + (quad & 1) * 16;
                uint32_t o = swz(brow, bkb);
                ldmx4(bh[bi * 2][0], bh[bi * 2][1], bh[bi * 2 + 1][0], bh[bi * 2 + 1][1],
                      tBh + o);
                ldmx4(bl[bi * 2][0], bl[bi * 2][1], bl[bi * 2 + 1][0], bl[bi * 2 + 1][1],
                      tBl + o);
            }
#pragma unroll
            for (int mi = 0; mi < 4; mi++) {
#pragma unroll
                for (int ni = 0; ni < 4; ni++) {
                    float* d = acc[mi][ni];
                    mma16816(d[0], d[1], d[2], d[3],
                             ah[mi][0], ah[mi][1], ah[mi][2], ah[mi][3],
                             bh[ni][0], bh[ni][1]);
                    mma16816(d[0], d[1], d[2], d[3],
                             ah[mi][0], ah[mi][1], ah[mi][2], ah[mi][3],
                             bl[ni][0], bl[ni][1]);
                }
            }
        }
    }

    const int g = lane >> 2;
    const int ti = lane & 3;
#pragma unroll
    for (int mi = 0; mi < 4; mi++) {
#pragma unroll
        for (int ni = 0; ni < 4; ni++) {
            size_t row = m0 + wm * 64 + mi * 16 + g;
            size_t col = n0 + wn * 32 + ni * 8 + 2 * ti;
            float* a = acc[mi][ni];
            if (split_out) {
                __half h0 = __float2half_rn(a[0]);
                __half h1 = __float2half_rn(a[1]);
                __half h2 = __float2half_rn(a[2]);
                __half h3 = __float2half_rn(a[3]);
                *reinterpret_cast<__half2*>(Chi + row * N + col) = __halves2half2(h0, h1);
                *reinterpret_cast<__half2*>(Chi + (row + 8) * N + col) = __halves2half2(h2, h3);
                *reinterpret_cast<__half2*>(Clo + row * N + col) =
                    __floats2half2_rn(a[0] - __half2float(h0), a[1] - __half2float(h1));
                *reinterpret_cast<__half2*>(Clo + (row + 8) * N + col) =
                    __floats2half2_rn(a[2] - __half2float(h2), a[3] - __half2float(h3));
            } else {
                *reinterpret_cast<float2*>(Cout + row * N + col) =
                    make_float2(a[0], a[1]);
                *reinterpret_cast<float2*>(Cout + (row + 8) * N + col) =
                    make_float2(a[2], a[3]);
            }
        }
    }
}

// ---------------- tensor-core flash attention (causal, fp16 3-term) --------
// CTA: 128 q rows, 8 warps x 16 rows. KV tiles of 64, 4-stage, 1 barrier/tile.
// SMEM: Q (hi+lo) 32KB at offset 0, then 4 KV stages x 32KB.
#define AT_TILE 8192          // 64 rows x 128B
#define AT_STAGE (4 * AT_TILE)
#define AT_QB 32768
#define AT_SMEM (AT_QB + 4 * AT_STAGE)
#define SCALE_LOG2E 0.1803368801111204f   // (1/8) * log2(e)

__global__ __launch_bounds__(256, 1)
void flash_attn_mma(const __half* __restrict__ qh, const __half* __restrict__ ql,
                    __half* __restrict__ yh)
{
    extern __shared__ char smem[];
    const uint32_t sbase = smem_u32(smem);
    const int tid = threadIdx.x;
    const int wid = tid >> 5;
    const int lane = tid & 31;
    const int quad = lane >> 3;
    const int qr = lane & 7;
    const int b = blockIdx.z;
    const int h = blockIdx.y;
    const int qt = gridDim.x - 1 - blockIdx.x;
    const int q0 = qt * 128;
    const int nt = 2 * qt + 2;

    const size_t bbase = (size_t)(b * T_) * C3_;
    const __half* qsh = qh + bbase + h * D_;
    const __half* qsl = ql + bbase + h * D_;
    const __half* ksh = qh + bbase + C_ + h * D_;
    const __half* ksl = ql + bbase + C_ + h * D_;
    const __half* vsh = qh + bbase + 2 * C_ + h * D_;
    const __half* vsl = ql + bbase + 2 * C_ + h * D_;

    auto issue_kv = [&](int t, int stage) {
        const int j0 = t * 64;
#pragma unroll
        for (int it = 0; it < 8; it++) {
            const int tile = it >> 1;
            const uint32_t r = (it & 1) * 32 + (tid >> 3);
            const uint32_t c16 = tid & 7;
            const __half* src =
                (tile == 0 ? ksh : tile == 1 ? ksl : tile == 2 ? vsh : vsl)
                + (size_t)(j0 + r) * C3_ + c16 * 8;
            cp_async16(sbase + AT_QB + stage * AT_STAGE + tile * AT_TILE
                       + swz(r, c16 * 16u), src);
        }
        cp_commit();
    };

    // group 0: Q hi+lo; groups 1-3: kv tiles 0-2
#pragma unroll
    for (int it = 0; it < 8; it++) {
        const int half = it >> 2;
        const uint32_t r = (it & 3) * 32 + (tid >> 3);
        const uint32_t c16 = tid & 7;
        const __half* src = (half == 0 ? qsh : qsl) + (size_t)(q0 + r) * C3_ + c16 * 8;
        cp_async16(sbase + half * 16384 + swz(r, c16 * 16u), src);
    }
    cp_commit();
    issue_kv(0, 0);
    issue_kv(1, 1);
    issue_kv(2, 2);
    cp_wait3();       // Q resident
    __syncthreads();

    // Q fragments (Q region never rewritten)
    uint32_t Qh[4][4], Ql[4][4];
#pragma unroll
    for (int kf = 0; kf < 4; kf++) {
        uint32_t arow = wid * 16 + (quad & 1) * 8 + qr;
        uint32_t akb = kf * 32 + (quad >> 1) * 16;
        uint32_t o = swz(arow, akb);
        ldmx4(Qh[kf][0], Qh[kf][1], Qh[kf][2], Qh[kf][3], sbase + o);
        ldmx4(Ql[kf][0], Ql[kf][1], Ql[kf][2], Ql[kf][3], sbase + 16384 + o);
    }

    float O[8][4];
#pragma unroll
    for (int i = 0; i < 8; i++)
#pragma unroll
        for (int r = 0; r < 4; r++) O[i][r] = 0.f;
    float m0r = -1e30f, m1r = -1e30f, l0r = 0.f, l1r = 0.f;
    const int row_lo = q0 + wid * 16 + (lane >> 2);

    for (int t = 0; t < nt; t++) {
        const int s = t & 3;
        cp_wait2();            // kv tile t resident
        __syncthreads();       // publish stage s; retire stage (t+3)&3
        if (t + 3 < nt) issue_kv(t + 3, (t + 3) & 3);
        else cp_commit();

        const int j0 = t * 64;
        const uint32_t stage = sbase + AT_QB + s * AT_STAGE;
        const uint32_t tKh = stage + 0 * AT_TILE;
        const uint32_t tKl = stage + 1 * AT_TILE;
        const uint32_t tVh = stage + 2 * AT_TILE;
        const uint32_t tVl = stage + 3 * AT_TILE;

        // ---- S = Q K^T (3-term) ----
        float S[8][4];
#pragma unroll
        for (int i = 0; i < 8; i++)
#pragma unroll
            for (int r = 0; r < 4; r++) S[i][r] = 0.f;

#pragma unroll
        for (int kf = 0; kf < 4; kf++) {
            uint32_t bh[8][2], bl[8][2];
#pragma unroll
            for (int bi = 0; bi < 4; bi++) {
                uint32_t brow = bi * 16 + (quad >> 1) * 8 + qr;
                uint32_t bkb = kf * 32 + (quad & 1) * 16;
                uint32_t o = swz(brow, bkb);
                ldmx4(bh[bi * 2][0], bh[bi * 2][1], bh[bi * 2 + 1][0], bh[bi * 2 + 1][1],
                      tKh + o);
                ldmx4(bl[bi * 2][0], bl[bi * 2][1], bl[bi * 2 + 1][0], bl[bi * 2 + 1][1],
                      tKl + o);
            }
#pragma unroll
            for (int nf = 0; nf < 8; nf++) {
                mma16816(S[nf][0], S[nf][1], S[nf][2], S[nf][3],
                         Qh[kf][0], Qh[kf][1], Qh[kf][2], Qh[kf][3],
                         bh[nf][0], bh[nf][1]);
                mma16816(S[nf][0], S[nf][1], S[nf][2], S[nf][3],
                         Qh[kf][0], Qh[kf][1], Qh[kf][2], Qh[kf][3],
                         bl[nf][0], bl[nf][1]);
                mma16816(S[nf][0], S[nf][1], S[nf][2], S[nf][3],
                         Ql[kf][0], Ql[kf][1], Ql[kf][2], Ql[kf][3],
                         bh[nf][0], bh[nf][1]);
            }
        }

        // scale + causal mask
#pragma unroll
        for (int nf = 0; nf < 8; nf++)
#pragma unroll
            for (int r = 0; r < 4; r++) S[nf][r] *= SCALE_LOG2E;

        if (j0 + 63 > q0 + wid * 16) {
            const int kvb = j0 + 2 * (lane & 3);
#pragma unroll
            for (int nf = 0; nf < 8; nf++) {
                const int kv = kvb + nf * 8;
                if (kv     > row_lo)     S[nf][0] = -1e30f;
                if (kv + 1 > row_lo)     S[nf][1] = -1e30f;
                if (kv     > row_lo + 8) S[nf][2] = -1e30f;
                if (kv + 1 > row_lo + 8) S[nf][3] = -1e30f;
            }
        }

        // row max
        float rm0 = -1e30f, rm1 = -1e30f;
#pragma unroll
        for (int nf = 0; nf < 8; nf++) {
            rm0 = fmaxf(rm0, fmaxf(S[nf][0], S[nf][1]));
            rm1 = fmaxf(rm1, fmaxf(S[nf][2], S[nf][3]));
        }
        rm0 = fmaxf(rm0, __shfl_xor_sync(0xffffffffu, rm0, 1));
        rm0 = fmaxf(rm0, __shfl_xor_sync(0xffffffffu, rm0, 2));
        rm1 = fmaxf(rm1, __shfl_xor_sync(0xffffffffu, rm1, 1));
        rm1 = fmaxf(rm1, __shfl_xor_sync(0xffffffffu, rm1, 2));

        const float mn0 = fmaxf(m0r, rm0);
        const float mn1 = fmaxf(m1r, rm1);
        const float cr0 = ex2(m0r - mn0);
        const float cr1 = ex2(m1r - mn1);
        m0r = mn0; m1r = mn1;

        float rs0 = 0.f, rs1 = 0.f;
#pragma unroll
        for (int nf = 0; nf < 8; nf++) {
            S[nf][0] = ex2(S[nf][0] - mn0);
            S[nf][1] = ex2(S[nf][1] - mn0);
            S[nf][2] = ex2(S[nf][2] - mn1);
            S[nf][3] = ex2(S[nf][3] - mn1);
            rs0 += S[nf][0] + S[nf][1];
            rs1 += S[nf][2] + S[nf][3];
        }
        rs0 += __shfl_xor_sync(0xffffffffu, rs0, 1);
        rs0 += __shfl_xor_sync(0xffffffffu, rs0, 2);
        rs1 += __shfl_xor_sync(0xffffffffu, rs1, 1);
        rs1 += __shfl_xor_sync(0xffffffffu, rs1, 2);
        l0r = l0r * cr0 + rs0;
        l1r = l1r * cr1 + rs1;

#pragma unroll
        for (int nf = 0; nf < 8; nf++) {
            O[nf][0] *= cr0; O[nf][1] *= cr0;
            O[nf][2] *= cr1; O[nf][3] *= cr1;
        }

        // ---- O += P V (3-term) ----
#pragma unroll
        for (int kf = 0; kf < 4; kf++) {
            uint32_t pah[4], pal[4];
#pragma unroll
            for (int half = 0; half < 2; half++) {
                float p0 = S[2 * kf + half][0], p1 = S[2 * kf + half][1];
                float p2 = S[2 * kf + half][2], p3 = S[2 * kf + half][3];
                __half h0 = __float2half_rn(p0);
                __half h1 = __float2half_rn(p1);
                __half h2 = __float2half_rn(p2);
                __half h3 = __float2half_rn(p3);
                __half2 t01 = __halves2half2(h0, h1);
                __half2 t23 = __halves2half2(h2, h3);
                pah[2 * half + 0] = *reinterpret_cast<uint32_t*>(&t01);
                pah[2 * half + 1] = *reinterpret_cast<uint32_t*>(&t23);
                pal[2 * half + 0] = packh2(p0 - __half2float(h0), p1 - __half2float(h1));
                pal[2 * half + 1] = packh2(p2 - __half2float(h2), p3 - __half2float(h3));
            }
            uint32_t vh[8][2], vl[8][2];
#pragma unroll
            for (int bi = 0; bi < 4; bi++) {
                uint32_t vrow = kf * 16 + (quad & 1) * 8 + qr;
                uint32_t vcb = bi * 32 + (quad >> 1) * 16;
                uint32_t o = swz(vrow, vcb);
                ldmx4t(vh[bi * 2][0], vh[bi * 2][1], vh[bi * 2 + 1][0],
                       vh[bi * 2 + 1][1], tVh + o);
                ldmx4t(vl[bi * 2][0], vl[bi * 2][1], vl[bi * 2 + 1][0],
                       vl[bi * 2 + 1][1], tVl + o);
            }
#pragma unroll
            for (int nf = 0; nf < 8; nf++) {
                mma16816(O[nf][0], O[nf][1], O[nf][2], O[nf][3],
                         pah[0], pah[1], pah[2], pah[3], vh[nf][0], vh[nf][1]);
                mma16816(O[nf][0], O[nf][1], O[nf][2], O[nf][3],
                         pah[0], pah[1], pah[2], pah[3], vl[nf][0], vl[nf][1]);
                mma16816(O[nf][0], O[nf][1], O[nf][2], O[nf][3],
                         pal[0], pal[1], pal[2], pal[3], vh[nf][0], vh[nf][1]);
            }
        }
    }

    // ---- epilogue: normalize, store hi only (proj is 2-term) ----
    const float li0 = 1.f / l0r;
    const float li1 = 1.f / l1r;
    const size_t r0 = (size_t)(b * T_) + row_lo;
    const int colb = h * D_ + 2 * (lane & 3);
#pragma unroll
    for (int nf = 0; nf < 8; nf++) {
        float o0 = O[nf][0] * li0, o1 = O[nf][1] * li0;
        float o2 = O[nf][2] * li1, o3 = O[nf][3] * li1;
        const size_t c = colb + nf * 8;
        *reinterpret_cast<__half2*>(yh + r0 * C_ + c) = __floats2half2_rn(o0, o1);
        *reinterpret_cast<__half2*>(yh + (r0 + 8) * C_ + c) = __floats2half2_rn(o2, o3);
    }
}

// ---------------- launch ----------------
extern "C" void kernel_launch(void* const* d_in, const int* in_sizes, int n_in,
                              void* d_out, int out_size)
{
    const float* x      = (const float*)d_in[0];
    const float* w_attn = (const float*)d_in[1];
    const float* w_proj = (const float*)d_in[2];
    float* out = (float*)d_out;

    __half *xhi, *wahi, *walo, *wphi, *wplo, *qkvh, *qkvl, *yhi;
    cudaGetSymbolAddress((void**)&xhi, g_xhi);
    cudaGetSymbolAddress((void**)&wahi, g_wahi);
    cudaGetSymbolAddress((void**)&walo, g_walo);
    cudaGetSymbolAddress((void**)&wphi, g_wphi);
    cudaGetSymbolAddress((void**)&wplo, g_wplo);
    cudaGetSymbolAddress((void**)&qkvh, g_qkvh);
    cudaGetSymbolAddress((void**)&qkvl, g_qkvl);
    cudaGetSymbolAddress((void**)&yhi, g_yhi);

    cudaFuncSetAttribute(gemm_mma, cudaFuncAttributeMaxDynamicSharedMemorySize, GEMM_SMEM);
    cudaFuncSetAttribute(flash_attn_mma, cudaFuncAttributeMaxDynamicSharedMemorySize, AT_SMEM);

    {
        int n4 = M_ROWS * C_ / 4;
        trunc_f16<<<(n4 + 255) / 256, 256>>>((const float4*)x, (__half2*)xhi, n4);
    }
    {
        int n4 = C3_ * C_ / 4;
        split_f16<<<(n4 + 255) / 256, 256>>>((const float4*)w_attn,
            (__half2*)wahi, (__half2*)walo, n4);
    }
    {
        int n4 = C_ * C_ / 4;
        split_f16<<<(n4 + 255) / 256, 256>>>((const float4*)w_proj,
            (__half2*)wphi, (__half2*)wplo, n4);
    }

    // 1) QKV (2-term fp16): write fp16 hi/lo
    {
        dim3 g(C3_ / 128, M_ROWS / 128);
        gemm_mma<<<g, 256, GEMM_SMEM>>>(xhi, wahi, walo,
                                        nullptr, qkvh, qkvl, 1, M_ROWS, C3_, C_);
    }
    // 2) tensor-core flash attention (3-term fp16), writes yh only
    {
        dim3 g(T_ / 128, H_, B_);
        flash_attn_mma<<<g, 256, AT_SMEM>>>(qkvh, qkvl, yhi);
    }
    // 3) out = yh @ (Wph + Wpl)^T (2-term fp16, fp32 out)
    {
        dim3 g(C_ / 128, M_ROWS / 128);
        gemm_mma<<<g, 256, GEMM_SMEM>>>(yhi, wphi, wplo,
                                        out, nullptr, nullptr, 0, M_ROWS, C_, C_);
    }
}

// round 13
// speedup vs baseline: 6.1989x; 1.2509x over previous
#include <cuda_runtime.h>
#include <cuda_fp16.h>
#include <cstdint>

#define B_ 4
#define T_ 2048
#define C_ 1024
#define H_ 16
#define D_ 64
#define C3_ 3072
#define M_ROWS (B_ * T_)

// ---------------- scratch (device globals: allocation-free) ----------------
__device__ __half g_xhi[(size_t)M_ROWS * C_];
__device__ __half g_wahi[(size_t)C3_ * C_];
__device__ __half g_walo[(size_t)C3_ * C_];
__device__ __half g_wphi[(size_t)C_ * C_];
__device__ __half g_wplo[(size_t)C_ * C_];
__device__ __half g_qkvh[(size_t)M_ROWS * C3_];
__device__ __half g_qkvl[(size_t)M_ROWS * C3_];
__device__ __half g_yhi[(size_t)M_ROWS * C_];

// ---------------- helpers ----------------
__device__ __forceinline__ uint32_t smem_u32(const void* p) {
    uint32_t a;
    asm("{ .reg .u64 t; cvta.to.shared.u64 t, %1; cvt.u32.u64 %0, t; }"
        : "=r"(a) : "l"(p));
    return a;
}
__device__ __forceinline__ void cp_async16(uint32_t dst, const void* src) {
    asm volatile("cp.async.cg.shared.global [%0], [%1], 16;" :: "r"(dst), "l"(src));
}
__device__ __forceinline__ void cp_commit() {
    asm volatile("cp.async.commit_group;" ::: "memory");
}
__device__ __forceinline__ void cp_wait1() {
    asm volatile("cp.async.wait_group 1;" ::: "memory");
}
__device__ __forceinline__ void cp_wait2() {
    asm volatile("cp.async.wait_group 2;" ::: "memory");
}
__device__ __forceinline__ void ldmx4(uint32_t& r0, uint32_t& r1, uint32_t& r2,
                                      uint32_t& r3, uint32_t addr) {
    asm volatile("ldmatrix.sync.aligned.m8n8.x4.shared.b16 {%0,%1,%2,%3}, [%4];"
                 : "=r"(r0), "=r"(r1), "=r"(r2), "=r"(r3) : "r"(addr));
}
__device__ __forceinline__ void ldmx4t(uint32_t& r0, uint32_t& r1, uint32_t& r2,
                                       uint32_t& r3, uint32_t addr) {
    asm volatile("ldmatrix.sync.aligned.m8n8.x4.trans.shared.b16 {%0,%1,%2,%3}, [%4];"
                 : "=r"(r0), "=r"(r1), "=r"(r2), "=r"(r3) : "r"(addr));
}
__device__ __forceinline__ void mma16816(float& d0, float& d1, float& d2, float& d3,
                                         uint32_t a0, uint32_t a1, uint32_t a2, uint32_t a3,
                                         uint32_t b0, uint32_t b1) {
    asm volatile("mma.sync.aligned.m16n8k16.row.col.f32.f16.f16.f32 "
                 "{%0,%1,%2,%3}, {%4,%5,%6,%7}, {%8,%9}, {%0,%1,%2,%3};"
                 : "+f"(d0), "+f"(d1), "+f"(d2), "+f"(d3)
                 : "r"(a0), "r"(a1), "r"(a2), "r"(a3), "r"(b0), "r"(b1));
}
__device__ __forceinline__ float ex2(float x) {
    float y;
    asm("ex2.approx.ftz.f32 %0, %1;" : "=f"(y) : "f"(x));
    return y;
}
// swizzled byte offset: row-major 128B rows, xor bits 4-6 by row&7
__device__ __forceinline__ uint32_t swz(uint32_t row, uint32_t kb) {
    return row * 128u + (kb ^ ((row & 7u) * 16u));
}

// ---------------- fp32 -> fp16 (hi only / hi+lo) ----------------
__global__ __launch_bounds__(256)
void trunc_f16(const float4* __restrict__ in, __half2* __restrict__ hi, int n4)
{
    int i = blockIdx.x * 256 + threadIdx.x;
    if (i >= n4) return;
    float4 v = in[i];
    hi[2 * i + 0] = __floats2half2_rn(v.x, v.y);
    hi[2 * i + 1] = __floats2half2_rn(v.z, v.w);
}

__global__ __launch_bounds__(256)
void split_f16(const float4* __restrict__ in, __half2* __restrict__ hi,
               __half2* __restrict__ lo, int n4)
{
    int i = blockIdx.x * 256 + threadIdx.x;
    if (i >= n4) return;
    float4 v = in[i];
    __half h0 = __float2half_rn(v.x);
    __half h1 = __float2half_rn(v.y);
    __half h2 = __float2half_rn(v.z);
    __half h3 = __float2half_rn(v.w);
    hi[2 * i + 0] = __halves2half2(h0, h1);
    hi[2 * i + 1] = __halves2half2(h2, h3);
    lo[2 * i + 0] = __floats2half2_rn(v.x - __half2float(h0), v.y - __half2float(h1));
    lo[2 * i + 1] = __floats2half2_rn(v.z - __half2float(h2), v.w - __half2float(h3));
}

// ---------------- mma.sync GEMM: C = Ah @ (Wh+Wl)^T (2-term fp16) ----------
// Tile 128x64 per CTA, 128 threads (4 warps: 2M x 2N, warp 64x32).
// 3-stage pipeline, 32KB/stage, 96KB/CTA -> 2 CTAs/SM. Single barrier/chunk.
#define TILE_A 16384           // 128 rows x 128B
#define TILE_BB 8192           // 64 rows x 128B
#define G_STAGE (TILE_A + 2 * TILE_BB)   // 32KB
#define GEMM_SMEM (3 * G_STAGE)          // 96KB

__global__ __launch_bounds__(128, 2)
void gemm_mma(const __half* __restrict__ Ahi,
              const __half* __restrict__ Bhi, const __half* __restrict__ Blo,
              float* __restrict__ Cout, __half* __restrict__ Chi,
              __half* __restrict__ Clo, int split_out, int M, int N, int K)
{
    extern __shared__ char smem[];
    const uint32_t sbase = smem_u32(smem);
    const int tid = threadIdx.x;
    const int wid = tid >> 5;
    const int lane = tid & 31;
    const int wm = wid & 1;          // M offset 0/64
    const int wn = wid >> 1;         // N offset 0/32
    const size_t m0 = (size_t)blockIdx.y * 128;
    const size_t n0 = (size_t)blockIdx.x * 64;
    const int quad = lane >> 3;
    const int qr = lane & 7;

    float acc[4][4][4];
#pragma unroll
    for (int i = 0; i < 4; i++)
#pragma unroll
        for (int j = 0; j < 4; j++)
#pragma unroll
            for (int r = 0; r < 4; r++) acc[i][j][r] = 0.f;

    const int NCH = K >> 6;

    auto issue_chunk = [&](int ch, int st) {
        const int k0 = ch * 64;
        char* base = smem + st * G_STAGE;
#pragma unroll
        for (int it = 0; it < 8; it++) {       // A: 1024 chunks
            int idx = it * 128 + tid;
            uint32_t row = idx >> 3, c16 = idx & 7;
            cp_async16(smem_u32(base + swz(row, c16 * 16u)),
                       Ahi + (m0 + row) * (size_t)K + k0 + c16 * 8);
        }
#pragma unroll
        for (int it = 0; it < 4; it++) {       // Bh + Bl: 512 chunks each
            int idx = it * 128 + tid;
            uint32_t row = idx >> 3, c16 = idx & 7;
            size_t off = (n0 + row) * (size_t)K + k0 + c16 * 8;
            uint32_t so = swz(row, c16 * 16u);
            cp_async16(smem_u32(base + TILE_A + so), Bhi + off);
            cp_async16(smem_u32(base + TILE_A + TILE_BB + so), Blo + off);
        }
        cp_commit();
    };

    issue_chunk(0, 0);
    issue_chunk(1, 1);

    for (int ch = 0; ch < NCH; ch++) {
        const int s = ch % 3;
        cp_wait1();            // chunk ch resident (ch+1 may pend)
        __syncthreads();       // all warps done with ch-1 -> stage (ch+2)%3 free
        if (ch + 2 < NCH) issue_chunk(ch + 2, (ch + 2) % 3);
        else cp_commit();

        const uint32_t tA  = sbase + s * G_STAGE;
        const uint32_t tBh = tA + TILE_A;
        const uint32_t tBl = tBh + TILE_BB;

#pragma unroll
        for (int kk = 0; kk < 4; kk++) {
            const uint32_t kb = kk * 32;
            uint32_t ah[4][4];
#pragma unroll
            for (int mi = 0; mi < 4; mi++) {
                uint32_t arow = wm * 64 + mi * 16 + (quad & 1) * 8 + qr;
                uint32_t akb = kb + (quad >> 1) * 16;
                ldmx4(ah[mi][0], ah[mi][1], ah[mi][2], ah[mi][3], tA + swz(arow, akb));
            }
            uint32_t bh[4][2], bl[4][2];
#pragma unroll
            for (int bi = 0; bi < 2; bi++) {
                uint32_t brow = wn * 32 + bi * 16 + (quad >> 1) * 8 + qr;
                uint32_t bkb = kb + (quad & 1) * 16;
                uint32_t o = swz(brow, bkb);
                ldmx4(bh[bi * 2][0], bh[bi * 2][1], bh[bi * 2 + 1][0], bh[bi * 2 + 1][1],
                      tBh + o);
                ldmx4(bl[bi * 2][0], bl[bi * 2][1], bl[bi * 2 + 1][0], bl[bi * 2 + 1][1],
                      tBl + o);
            }
#pragma unroll
            for (int mi = 0; mi < 4; mi++) {
#pragma unroll
                for (int ni = 0; ni < 4; ni++) {
                    float* d = acc[mi][ni];
                    mma16816(d[0], d[1], d[2], d[3],
                             ah[mi][0], ah[mi][1], ah[mi][2], ah[mi][3],
                             bh[ni][0], bh[ni][1]);
                    mma16816(d[0], d[1], d[2], d[3],
                             ah[mi][0], ah[mi][1], ah[mi][2], ah[mi][3],
                             bl[ni][0], bl[ni][1]);
                }
            }
        }
    }

    const int g = lane >> 2;
    const int ti = lane & 3;
#pragma unroll
    for (int mi = 0; mi < 4; mi++) {
#pragma unroll
        for (int ni = 0; ni < 4; ni++) {
            size_t row = m0 + wm * 64 + mi * 16 + g;
            size_t col = n0 + wn * 32 + ni * 8 + 2 * ti;
            float* a = acc[mi][ni];
            if (split_out) {
                __half h0 = __float2half_rn(a[0]);
                __half h1 = __float2half_rn(a[1]);
                __half h2 = __float2half_rn(a[2]);
                __half h3 = __float2half_rn(a[3]);
                *reinterpret_cast<__half2*>(Chi + row * N + col) = __halves2half2(h0, h1);
                *reinterpret_cast<__half2*>(Chi + (row + 8) * N + col) = __halves2half2(h2, h3);
                *reinterpret_cast<__half2*>(Clo + row * N + col) =
                    __floats2half2_rn(a[0] - __half2float(h0), a[1] - __half2float(h1));
                *reinterpret_cast<__half2*>(Clo + (row + 8) * N + col) =
                    __floats2half2_rn(a[2] - __half2float(h2), a[3] - __half2float(h3));
            } else {
                *reinterpret_cast<float2*>(Cout + row * N + col) =
                    make_float2(a[0], a[1]);
                *reinterpret_cast<float2*>(Cout + (row + 8) * N + col) =
                    make_float2(a[2], a[3]);
            }
        }
    }
}

// ---------------- tensor-core flash attention (causal, 2-term fp16) --------
// CTA: 64 q rows, 4 warps x 16 rows, 128 threads. KV tiles of 64, 3-stage.
// SMEM: Qh 8KB + 3 x 32KB KV = 104KB -> 2 CTAs/SM. Single barrier/tile.
// S = Qh(Kh+Kl)^T ; O += Ph(Vh+Vl)
#define AT_TILE 8192          // 64 rows x 128B
#define AT_STAGE (4 * AT_TILE)
#define AT_QB 8192
#define AT_SMEM (AT_QB + 3 * AT_STAGE)
#define SCALE_LOG2E 0.1803368801111204f   // (1/8) * log2(e)

__global__ __launch_bounds__(128, 2)
void flash_attn_mma(const __half* __restrict__ qh, const __half* __restrict__ ql,
                    __half* __restrict__ yh)
{
    extern __shared__ char smem[];
    const uint32_t sbase = smem_u32(smem);
    const int tid = threadIdx.x;
    const int wid = tid >> 5;
    const int lane = tid & 31;
    const int quad = lane >> 3;
    const int qr = lane & 7;
    const int b = blockIdx.z;
    const int h = blockIdx.y;
    const int qt = gridDim.x - 1 - blockIdx.x;
    const int q0 = qt * 64;
    const int nt = qt + 1;

    const size_t bbase = (size_t)(b * T_) * C3_;
    const __half* qsh = qh + bbase + h * D_;
    const __half* ksh = qh + bbase + C_ + h * D_;
    const __half* ksl = ql + bbase + C_ + h * D_;
    const __half* vsh = qh + bbase + 2 * C_ + h * D_;
    const __half* vsl = ql + bbase + 2 * C_ + h * D_;

    auto issue_kv = [&](int t, int stage) {
        const int j0 = t * 64;
        const uint32_t kvb = sbase + AT_QB + stage * AT_STAGE;
#pragma unroll
        for (int it = 0; it < 4; it++) {
            int idx = it * 128 + tid;               // 512 chunks per tile
            uint32_t r = idx >> 3, c16 = idx & 7;
            size_t off = (size_t)(j0 + r) * C3_ + c16 * 8;
            uint32_t so = swz(r, c16 * 16u);
            cp_async16(kvb + 0 * AT_TILE + so, ksh + off);
            cp_async16(kvb + 1 * AT_TILE + so, ksl + off);
            cp_async16(kvb + 2 * AT_TILE + so, vsh + off);
            cp_async16(kvb + 3 * AT_TILE + so, vsl + off);
        }
        cp_commit();
    };

    // group 0: Qh (64 rows x 8 chunks = 512)
#pragma unroll
    for (int it = 0; it < 4; it++) {
        int idx = it * 128 + tid;
        uint32_t r = idx >> 3, c16 = idx & 7;
        cp_async16(sbase + swz(r, c16 * 16u), qsh + (size_t)(q0 + r) * C3_ + c16 * 8);
    }
    cp_commit();
    issue_kv(0, 0);
    if (nt > 1) issue_kv(1, 1); else cp_commit();
    cp_wait2();       // Q resident
    __syncthreads();

    uint32_t Qh[4][4];
#pragma unroll
    for (int kf = 0; kf < 4; kf++) {
        uint32_t arow = wid * 16 + (quad & 1) * 8 + qr;
        uint32_t akb = kf * 32 + (quad >> 1) * 16;
        ldmx4(Qh[kf][0], Qh[kf][1], Qh[kf][2], Qh[kf][3], sbase + swz(arow, akb));
    }

    float O[8][4];
#pragma unroll
    for (int i = 0; i < 8; i++)
#pragma unroll
        for (int r = 0; r < 4; r++) O[i][r] = 0.f;
    float m0r = -1e30f, m1r = -1e30f, l0r = 0.f, l1r = 0.f;
    const int row_lo = q0 + wid * 16 + (lane >> 2);

    for (int t = 0; t < nt; t++) {
        const int s = t % 3;
        cp_wait1();            // kv tile t resident
        __syncthreads();       // stage (t+2)%3 free (all warps done with t-1)
        if (t + 2 < nt) issue_kv(t + 2, (t + 2) % 3);
        else cp_commit();

        const int j0 = t * 64;
        const uint32_t stage = sbase + AT_QB + s * AT_STAGE;
        const uint32_t tKh = stage + 0 * AT_TILE;
        const uint32_t tKl = stage + 1 * AT_TILE;
        const uint32_t tVh = stage + 2 * AT_TILE;
        const uint32_t tVl = stage + 3 * AT_TILE;

        // ---- S = Qh (Kh + Kl)^T ----
        float S[8][4];
#pragma unroll
        for (int i = 0; i < 8; i++)
#pragma unroll
            for (int r = 0; r < 4; r++) S[i][r] = 0.f;

#pragma unroll
        for (int kf = 0; kf < 4; kf++) {
            uint32_t bh[8][2], bl[8][2];
#pragma unroll
            for (int bi = 0; bi < 4; bi++) {
                uint32_t brow = bi * 16 + (quad >> 1) * 8 + qr;
                uint32_t bkb = kf * 32 + (quad & 1) * 16;
                uint32_t o = swz(brow, bkb);
                ldmx4(bh[bi * 2][0], bh[bi * 2][1], bh[bi * 2 + 1][0], bh[bi * 2 + 1][1],
                      tKh + o);
                ldmx4(bl[bi * 2][0], bl[bi * 2][1], bl[bi * 2 + 1][0], bl[bi * 2 + 1][1],
                      tKl + o);
            }
#pragma unroll
            for (int nf = 0; nf < 8; nf++) {
                mma16816(S[nf][0], S[nf][1], S[nf][2], S[nf][3],
                         Qh[kf][0], Qh[kf][1], Qh[kf][2], Qh[kf][3],
                         bh[nf][0], bh[nf][1]);
                mma16816(S[nf][0], S[nf][1], S[nf][2], S[nf][3],
                         Qh[kf][0], Qh[kf][1], Qh[kf][2], Qh[kf][3],
                         bl[nf][0], bl[nf][1]);
            }
        }

        // scale + causal mask
#pragma unroll
        for (int nf = 0; nf < 8; nf++)
#pragma unroll
            for (int r = 0; r < 4; r++) S[nf][r] *= SCALE_LOG2E;

        if (j0 + 63 > q0 + wid * 16) {
            const int kvb = j0 + 2 * (lane & 3);
#pragma unroll
            for (int nf = 0; nf < 8; nf++) {
                const int kv = kvb + nf * 8;
                if (kv     > row_lo)     S[nf][0] = -1e30f;
                if (kv + 1 > row_lo)     S[nf][1] = -1e30f;
                if (kv     > row_lo + 8) S[nf][2] = -1e30f;
                if (kv + 1 > row_lo + 8) S[nf][3] = -1e30f;
            }
        }

        // row max
        float rm0 = -1e30f, rm1 = -1e30f;
#pragma unroll
        for (int nf = 0; nf < 8; nf++) {
            rm0 = fmaxf(rm0, fmaxf(S[nf][0], S[nf][1]));
            rm1 = fmaxf(rm1, fmaxf(S[nf][2], S[nf][3]));
        }
        rm0 = fmaxf(rm0, __shfl_xor_sync(0xffffffffu, rm0, 1));
        rm0 = fmaxf(rm0, __shfl_xor_sync(0xffffffffu, rm0, 2));
        rm1 = fmaxf(rm1, __shfl_xor_sync(0xffffffffu, rm1, 1));
        rm1 = fmaxf(rm1, __shfl_xor_sync(0xffffffffu, rm1, 2));

        const float mn0 = fmaxf(m0r, rm0);
        const float mn1 = fmaxf(m1r, rm1);
        const float cr0 = ex2(m0r - mn0);
        const float cr1 = ex2(m1r - mn1);
        m0r = mn0; m1r = mn1;

        float rs0 = 0.f, rs1 = 0.f;
#pragma unroll
        for (int nf = 0; nf < 8; nf++) {
            S[nf][0] = ex2(S[nf][0] - mn0);
            S[nf][1] = ex2(S[nf][1] - mn0);
            S[nf][2] = ex2(S[nf][2] - mn1);
            S[nf][3] = ex2(S[nf][3] - mn1);
            rs0 += S[nf][0] + S[nf][1];
            rs1 += S[nf][2] + S[nf][3];
        }
        rs0 += __shfl_xor_sync(0xffffffffu, rs0, 1);
        rs0 += __shfl_xor_sync(0xffffffffu, rs0, 2);
        rs1 += __shfl_xor_sync(0xffffffffu, rs1, 1);
        rs1 += __shfl_xor_sync(0xffffffffu, rs1, 2);
        l0r = l0r * cr0 + rs0;
        l1r = l1r * cr1 + rs1;

#pragma unroll
        for (int nf = 0; nf < 8; nf++) {
            O[nf][0] *= cr0; O[nf][1] *= cr0;
            O[nf][2] *= cr1; O[nf][3] *= cr1;
        }

        // ---- O += Ph (Vh + Vl) ----
#pragma unroll
        for (int kf = 0; kf < 4; kf++) {
            uint32_t pah[4];
#pragma unroll
            for (int half = 0; half < 2; half++) {
                __half2 t01 = __floats2half2_rn(S[2 * kf + half][0], S[2 * kf + half][1]);
                __half2 t23 = __floats2half2_rn(S[2 * kf + half][2], S[2 * kf + half][3]);
                pah[2 * half + 0] = *reinterpret_cast<uint32_t*>(&t01);
                pah[2 * half + 1] = *reinterpret_cast<uint32_t*>(&t23);
            }
            uint32_t vh[8][2], vl[8][2];
#pragma unroll
            for (int bi = 0; bi < 4; bi++) {
                uint32_t vrow = kf * 16 + (quad & 1) * 8 + qr;
                uint32_t vcb = bi * 32 + (quad >> 1) * 16;
                uint32_t o = swz(vrow, vcb);
                ldmx4t(vh[bi * 2][0], vh[bi * 2][1], vh[bi * 2 + 1][0],
                       vh[bi * 2 + 1][1], tVh + o);
                ldmx4t(vl[bi * 2][0], vl[bi * 2][1], vl[bi * 2 + 1][0],
                       vl[bi * 2 + 1][1], tVl + o);
            }
#pragma unroll
            for (int nf = 0; nf < 8; nf++) {
                mma16816(O[nf][0], O[nf][1], O[nf][2], O[nf][3],
                         pah[0], pah[1], pah[2], pah[3], vh[nf][0], vh[nf][1]);
                mma16816(O[nf][0], O[nf][1], O[nf][2], O[nf][3],
                         pah[0], pah[1], pah[2], pah[3], vl[nf][0], vl[nf][1]);
            }
        }
    }

    // ---- epilogue: normalize, store hi only (proj is 2-term) ----
    const float li0 = 1.f / l0r;
    const float li1 = 1.f / l1r;
    const size_t r0 = (size_t)(b * T_) + row_lo;
    const int colb = h * D_ + 2 * (lane & 3);
#pragma unroll
    for (int nf = 0; nf < 8; nf++) {
        const size_t c = colb + nf * 8;
        *reinterpret_cast<__half2*>(yh + r0 * C_ + c) =
            __floats2half2_rn(O[nf][0] * li0, O[nf][1] * li0);
        *reinterpret_cast<__half2*>(yh + (r0 + 8) * C_ + c) =
            __floats2half2_rn(O[nf][2] * li1, O[nf][3] * li1);
    }
}

// ---------------- launch ----------------
extern "C" void kernel_launch(void* const* d_in, const int* in_sizes, int n_in,
                              void* d_out, int out_size)
{
    const float* x      = (const float*)d_in[0];
    const float* w_attn = (const float*)d_in[1];
    const float* w_proj = (const float*)d_in[2];
    float* out = (float*)d_out;

    __half *xhi, *wahi, *walo, *wphi, *wplo, *qkvh, *qkvl, *yhi;
    cudaGetSymbolAddress((void**)&xhi, g_xhi);
    cudaGetSymbolAddress((void**)&wahi, g_wahi);
    cudaGetSymbolAddress((void**)&walo, g_walo);
    cudaGetSymbolAddress((void**)&wphi, g_wphi);
    cudaGetSymbolAddress((void**)&wplo, g_wplo);
    cudaGetSymbolAddress((void**)&qkvh, g_qkvh);
    cudaGetSymbolAddress((void**)&qkvl, g_qkvl);
    cudaGetSymbolAddress((void**)&yhi, g_yhi);

    cudaFuncSetAttribute(gemm_mma, cudaFuncAttributeMaxDynamicSharedMemorySize, GEMM_SMEM);
    cudaFuncSetAttribute(flash_attn_mma, cudaFuncAttributeMaxDynamicSharedMemorySize, AT_SMEM);

    {
        int n4 = M_ROWS * C_ / 4;
        trunc_f16<<<(n4 + 255) / 256, 256>>>((const float4*)x, (__half2*)xhi, n4);
    }
    {
        int n4 = C3_ * C_ / 4;
        split_f16<<<(n4 + 255) / 256, 256>>>((const float4*)w_attn,
            (__half2*)wahi, (__half2*)walo, n4);
    }
    {
        int n4 = C_ * C_ / 4;
        split_f16<<<(n4 + 255) / 256, 256>>>((const float4*)w_proj,
            (__half2*)wphi, (__half2*)wplo, n4);
    }

    // 1) QKV (2-term fp16): write fp16 hi/lo
    {
        dim3 g(C3_ / 64, M_ROWS / 128);
        gemm_mma<<<g, 128, GEMM_SMEM>>>(xhi, wahi, walo,
                                        nullptr, qkvh, qkvl, 1, M_ROWS, C3_, C_);
    }
    // 2) tensor-core flash attention (2-term fp16), writes yh only
    {
        dim3 g(T_ / 64, H_, B_);
        flash_attn_mma<<<g, 128, AT_SMEM>>>(qkvh, qkvl, yhi);
    }
    // 3) out = yh @ (Wph + Wpl)^T (2-term fp16, fp32 out)
    {
        dim3 g(C_ / 64, M_ROWS / 128);
        gemm_mma<<<g, 128, GEMM_SMEM>>>(yhi, wphi, wplo,
                                        out, nullptr, nullptr, 0, M_ROWS, C_, C_);
    }
}

// round 14
// speedup vs baseline: 8.0621x; 1.3006x over previous
#include <cuda_runtime.h>
#include <cuda_fp16.h>
#include <cstdint>

#define B_ 4
#define T_ 2048
#define C_ 1024
#define H_ 16
#define D_ 64
#define C3_ 3072
#define M_ROWS (B_ * T_)

// ---------------- scratch (device globals: allocation-free) ----------------
__device__ __half g_xhi[(size_t)M_ROWS * C_];
__device__ __half g_wahi[(size_t)C3_ * C_];
__device__ __half g_wphi[(size_t)C_ * C_];
__device__ __half g_qkvh[(size_t)M_ROWS * C3_];
__device__ __half g_qkvl[(size_t)M_ROWS * C3_];
__device__ __half g_yhi[(size_t)M_ROWS * C_];

// ---------------- helpers ----------------
__device__ __forceinline__ uint32_t smem_u32(const void* p) {
    uint32_t a;
    asm("{ .reg .u64 t; cvta.to.shared.u64 t, %1; cvt.u32.u64 %0, t; }"
        : "=r"(a) : "l"(p));
    return a;
}
__device__ __forceinline__ void cp_async16(uint32_t dst, const void* src) {
    asm volatile("cp.async.cg.shared.global [%0], [%1], 16;" :: "r"(dst), "l"(src));
}
__device__ __forceinline__ void cp_commit() {
    asm volatile("cp.async.commit_group;" ::: "memory");
}
__device__ __forceinline__ void cp_wait1() {
    asm volatile("cp.async.wait_group 1;" ::: "memory");
}
__device__ __forceinline__ void cp_wait2() {
    asm volatile("cp.async.wait_group 2;" ::: "memory");
}
__device__ __forceinline__ void ldmx4(uint32_t& r0, uint32_t& r1, uint32_t& r2,
                                      uint32_t& r3, uint32_t addr) {
    asm volatile("ldmatrix.sync.aligned.m8n8.x4.shared.b16 {%0,%1,%2,%3}, [%4];"
                 : "=r"(r0), "=r"(r1), "=r"(r2), "=r"(r3) : "r"(addr));
}
__device__ __forceinline__ void ldmx4t(uint32_t& r0, uint32_t& r1, uint32_t& r2,
                                       uint32_t& r3, uint32_t addr) {
    asm volatile("ldmatrix.sync.aligned.m8n8.x4.trans.shared.b16 {%0,%1,%2,%3}, [%4];"
                 : "=r"(r0), "=r"(r1), "=r"(r2), "=r"(r3) : "r"(addr));
}
__device__ __forceinline__ void mma16816(float& d0, float& d1, float& d2, float& d3,
                                         uint32_t a0, uint32_t a1, uint32_t a2, uint32_t a3,
                                         uint32_t b0, uint32_t b1) {
    asm volatile("mma.sync.aligned.m16n8k16.row.col.f32.f16.f16.f32 "
                 "{%0,%1,%2,%3}, {%4,%5,%6,%7}, {%8,%9}, {%0,%1,%2,%3};"
                 : "+f"(d0), "+f"(d1), "+f"(d2), "+f"(d3)
                 : "r"(a0), "r"(a1), "r"(a2), "r"(a3), "r"(b0), "r"(b1));
}
__device__ __forceinline__ float ex2(float x) {
    float y;
    asm("ex2.approx.ftz.f32 %0, %1;" : "=f"(y) : "f"(x));
    return y;
}
// swizzled byte offset: row-major 128B rows, xor bits 4-6 by row&7
__device__ __forceinline__ uint32_t swz(uint32_t row, uint32_t kb) {
    return row * 128u + (kb ^ ((row & 7u) * 16u));
}

// ---------------- fp32 -> fp16 (hi only / hi+lo) ----------------
__global__ __launch_bounds__(256)
void trunc_f16(const float4* __restrict__ in, __half2* __restrict__ hi, int n4)
{
    int i = blockIdx.x * 256 + threadIdx.x;
    if (i >= n4) return;
    float4 v = in[i];
    hi[2 * i + 0] = __floats2half2_rn(v.x, v.y);
    hi[2 * i + 1] = __floats2half2_rn(v.z, v.w);
}

// ---------------- mma.sync GEMM: C = Ah @ Wh^T (1-term fp16, 4-stage) ------
// Tile 128x64 per CTA, 128 threads (4 warps: 2M x 2N, warp 64x32).
// Stage = {A 16KB, B 8KB} = 24KB; 4 stages = 96KB/CTA -> 2 CTAs/SM.
#define TILE_A 16384           // 128 rows x 128B
#define TILE_BB 8192           // 64 rows x 128B
#define G_STAGE (TILE_A + TILE_BB)       // 24KB
#define GEMM_SMEM (4 * G_STAGE)          // 96KB

__global__ __launch_bounds__(128, 2)
void gemm_mma(const __half* __restrict__ Ahi, const __half* __restrict__ Bhi,
              float* __restrict__ Cout, __half* __restrict__ Chi,
              __half* __restrict__ Clo, int split_out, int M, int N, int K)
{
    extern __shared__ char smem[];
    const uint32_t sbase = smem_u32(smem);
    const int tid = threadIdx.x;
    const int wid = tid >> 5;
    const int lane = tid & 31;
    const int wm = wid & 1;          // M offset 0/64
    const int wn = wid >> 1;         // N offset 0/32
    const size_t m0 = (size_t)blockIdx.y * 128;
    const size_t n0 = (size_t)blockIdx.x * 64;
    const int quad = lane >> 3;
    const int qr = lane & 7;

    float acc[4][4][4];
#pragma unroll
    for (int i = 0; i < 4; i++)
#pragma unroll
        for (int j = 0; j < 4; j++)
#pragma unroll
            for (int r = 0; r < 4; r++) acc[i][j][r] = 0.f;

    const int NCH = K >> 6;

    auto issue_chunk = [&](int ch, int st) {
        const int k0 = ch * 64;
        char* base = smem + st * G_STAGE;
#pragma unroll
        for (int it = 0; it < 8; it++) {       // A: 1024 16B chunks
            int idx = it * 128 + tid;
            uint32_t row = idx >> 3, c16 = idx & 7;
            cp_async16(smem_u32(base + swz(row, c16 * 16u)),
                       Ahi + (m0 + row) * (size_t)K + k0 + c16 * 8);
        }
#pragma unroll
        for (int it = 0; it < 4; it++) {       // B: 512 chunks
            int idx = it * 128 + tid;
            uint32_t row = idx >> 3, c16 = idx & 7;
            cp_async16(smem_u32(base + TILE_A + swz(row, c16 * 16u)),
                       Bhi + (n0 + row) * (size_t)K + k0 + c16 * 8);
        }
        cp_commit();
    };

    issue_chunk(0, 0);
    issue_chunk(1, 1);
    issue_chunk(2, 2);

    for (int ch = 0; ch < NCH; ch++) {
        const int s = ch & 3;
        cp_wait2();            // chunk ch resident (ch+1, ch+2 may pend)
        __syncthreads();       // all warps done with ch-1 -> stage (ch+3)&3 free
        if (ch + 3 < NCH) issue_chunk(ch + 3, (ch + 3) & 3);
        else cp_commit();

        const uint32_t tA  = sbase + s * G_STAGE;
        const uint32_t tB = tA + TILE_A;

#pragma unroll
        for (int kk = 0; kk < 4; kk++) {
            const uint32_t kb = kk * 32;
            uint32_t ah[4][4];
#pragma unroll
            for (int mi = 0; mi < 4; mi++) {
                uint32_t arow = wm * 64 + mi * 16 + (quad & 1) * 8 + qr;
                uint32_t akb = kb + (quad >> 1) * 16;
                ldmx4(ah[mi][0], ah[mi][1], ah[mi][2], ah[mi][3], tA + swz(arow, akb));
            }
            uint32_t bh[4][2];
#pragma unroll
            for (int bi = 0; bi < 2; bi++) {
                uint32_t brow = wn * 32 + bi * 16 + (quad >> 1) * 8 + qr;
                uint32_t bkb = kb + (quad & 1) * 16;
                ldmx4(bh[bi * 2][0], bh[bi * 2][1], bh[bi * 2 + 1][0], bh[bi * 2 + 1][1],
                      tB + swz(brow, bkb));
            }
#pragma unroll
            for (int mi = 0; mi < 4; mi++) {
#pragma unroll
                for (int ni = 0; ni < 4; ni++) {
                    float* d = acc[mi][ni];
                    mma16816(d[0], d[1], d[2], d[3],
                             ah[mi][0], ah[mi][1], ah[mi][2], ah[mi][3],
                             bh[ni][0], bh[ni][1]);
                }
            }
        }
    }

    const int g = lane >> 2;
    const int ti = lane & 3;
#pragma unroll
    for (int mi = 0; mi < 4; mi++) {
#pragma unroll
        for (int ni = 0; ni < 4; ni++) {
            size_t row = m0 + wm * 64 + mi * 16 + g;
            size_t col = n0 + wn * 32 + ni * 8 + 2 * ti;
            float* a = acc[mi][ni];
            if (split_out) {
                __half h0 = __float2half_rn(a[0]);
                __half h1 = __float2half_rn(a[1]);
                __half h2 = __float2half_rn(a[2]);
                __half h3 = __float2half_rn(a[3]);
                *reinterpret_cast<__half2*>(Chi + row * N + col) = __halves2half2(h0, h1);
                *reinterpret_cast<__half2*>(Chi + (row + 8) * N + col) = __halves2half2(h2, h3);
                *reinterpret_cast<__half2*>(Clo + row * N + col) =
                    __floats2half2_rn(a[0] - __half2float(h0), a[1] - __half2float(h1));
                *reinterpret_cast<__half2*>(Clo + (row + 8) * N + col) =
                    __floats2half2_rn(a[2] - __half2float(h2), a[3] - __half2float(h3));
            } else {
                *reinterpret_cast<float2*>(Cout + row * N + col) =
                    make_float2(a[0], a[1]);
                *reinterpret_cast<float2*>(Cout + (row + 8) * N + col) =
                    make_float2(a[2], a[3]);
            }
        }
    }
}

// ---------------- tensor-core flash attention (causal, 2-term fp16) --------
// CTA: 64 q rows, 4 warps x 16 rows, 128 threads. KV tiles of 64, 3-stage.
// SMEM: Qh 8KB + 3 x 32KB KV = 104KB -> 2 CTAs/SM. Single barrier/tile.
// S = Qh(Kh+Kl)^T ; O += Ph(Vh+Vl)
#define AT_TILE 8192          // 64 rows x 128B
#define AT_STAGE (4 * AT_TILE)
#define AT_QB 8192
#define AT_SMEM (AT_QB + 3 * AT_STAGE)
#define SCALE_LOG2E 0.1803368801111204f   // (1/8) * log2(e)

__global__ __launch_bounds__(128, 2)
void flash_attn_mma(const __half* __restrict__ qh, const __half* __restrict__ ql,
                    __half* __restrict__ yh)
{
    extern __shared__ char smem[];
    const uint32_t sbase = smem_u32(smem);
    const int tid = threadIdx.x;
    const int wid = tid >> 5;
    const int lane = tid & 31;
    const int quad = lane >> 3;
    const int qr = lane & 7;
    const int b = blockIdx.z;
    const int h = blockIdx.y;
    const int qt = gridDim.x - 1 - blockIdx.x;
    const int q0 = qt * 64;
    const int nt = qt + 1;

    const size_t bbase = (size_t)(b * T_) * C3_;
    const __half* qsh = qh + bbase + h * D_;
    const __half* ksh = qh + bbase + C_ + h * D_;
    const __half* ksl = ql + bbase + C_ + h * D_;
    const __half* vsh = qh + bbase + 2 * C_ + h * D_;
    const __half* vsl = ql + bbase + 2 * C_ + h * D_;

    auto issue_kv = [&](int t, int stage) {
        const int j0 = t * 64;
        const uint32_t kvb = sbase + AT_QB + stage * AT_STAGE;
#pragma unroll
        for (int it = 0; it < 4; it++) {
            int idx = it * 128 + tid;               // 512 chunks per tile
            uint32_t r = idx >> 3, c16 = idx & 7;
            size_t off = (size_t)(j0 + r) * C3_ + c16 * 8;
            uint32_t so = swz(r, c16 * 16u);
            cp_async16(kvb + 0 * AT_TILE + so, ksh + off);
            cp_async16(kvb + 1 * AT_TILE + so, ksl + off);
            cp_async16(kvb + 2 * AT_TILE + so, vsh + off);
            cp_async16(kvb + 3 * AT_TILE + so, vsl + off);
        }
        cp_commit();
    };

    // group 0: Qh (64 rows x 8 chunks = 512)
#pragma unroll
    for (int it = 0; it < 4; it++) {
        int idx = it * 128 + tid;
        uint32_t r = idx >> 3, c16 = idx & 7;
        cp_async16(sbase + swz(r, c16 * 16u), qsh + (size_t)(q0 + r) * C3_ + c16 * 8);
    }
    cp_commit();
    issue_kv(0, 0);
    if (nt > 1) issue_kv(1, 1); else cp_commit();
    cp_wait2();       // Q resident
    __syncthreads();

    uint32_t Qh[4][4];
#pragma unroll
    for (int kf = 0; kf < 4; kf++) {
        uint32_t arow = wid * 16 + (quad & 1) * 8 + qr;
        uint32_t akb = kf * 32 + (quad >> 1) * 16;
        ldmx4(Qh[kf][0], Qh[kf][1], Qh[kf][2], Qh[kf][3], sbase + swz(arow, akb));
    }

    float O[8][4];
#pragma unroll
    for (int i = 0; i < 8; i++)
#pragma unroll
        for (int r = 0; r < 4; r++) O[i][r] = 0.f;
    float m0r = -1e30f, m1r = -1e30f, l0r = 0.f, l1r = 0.f;
    const int row_lo = q0 + wid * 16 + (lane >> 2);

    for (int t = 0; t < nt; t++) {
        const int s = t % 3;
        cp_wait1();            // kv tile t resident
        __syncthreads();       // stage (t+2)%3 free (all warps done with t-1)
        if (t + 2 < nt) issue_kv(t + 2, (t + 2) % 3);
        else cp_commit();

        const int j0 = t * 64;
        const uint32_t stage = sbase + AT_QB + s * AT_STAGE;
        const uint32_t tKh = stage + 0 * AT_TILE;
        const uint32_t tKl = stage + 1 * AT_TILE;
        const uint32_t tVh = stage + 2 * AT_TILE;
        const uint32_t tVl = stage + 3 * AT_TILE;

        // ---- S = Qh (Kh + Kl)^T ----
        float S[8][4];
#pragma unroll
        for (int i = 0; i < 8; i++)
#pragma unroll
            for (int r = 0; r < 4; r++) S[i][r] = 0.f;

#pragma unroll
        for (int kf = 0; kf < 4; kf++) {
            uint32_t bh[8][2], bl[8][2];
#pragma unroll
            for (int bi = 0; bi < 4; bi++) {
                uint32_t brow = bi * 16 + (quad >> 1) * 8 + qr;
                uint32_t bkb = kf * 32 + (quad & 1) * 16;
                uint32_t o = swz(brow, bkb);
                ldmx4(bh[bi * 2][0], bh[bi * 2][1], bh[bi * 2 + 1][0], bh[bi * 2 + 1][1],
                      tKh + o);
                ldmx4(bl[bi * 2][0], bl[bi * 2][1], bl[bi * 2 + 1][0], bl[bi * 2 + 1][1],
                      tKl + o);
            }
#pragma unroll
            for (int nf = 0; nf < 8; nf++) {
                mma16816(S[nf][0], S[nf][1], S[nf][2], S[nf][3],
                         Qh[kf][0], Qh[kf][1], Qh[kf][2], Qh[kf][3],
                         bh[nf][0], bh[nf][1]);
                mma16816(S[nf][0], S[nf][1], S[nf][2], S[nf][3],
                         Qh[kf][0], Qh[kf][1], Qh[kf][2], Qh[kf][3],
                         bl[nf][0], bl[nf][1]);
            }
        }

        // scale + causal mask
#pragma unroll
        for (int nf = 0; nf < 8; nf++)
#pragma unroll
            for (int r = 0; r < 4; r++) S[nf][r] *= SCALE_LOG2E;

        if (j0 + 63 > q0 + wid * 16) {
            const int kvb = j0 + 2 * (lane & 3);
#pragma unroll
            for (int nf = 0; nf < 8; nf++) {
                const int kv = kvb + nf * 8;
                if (kv     > row_lo)     S[nf][0] = -1e30f;
                if (kv + 1 > row_lo)     S[nf][1] = -1e30f;
                if (kv     > row_lo + 8) S[nf][2] = -1e30f;
                if (kv + 1 > row_lo + 8) S[nf][3] = -1e30f;
            }
        }

        // row max
        float rm0 = -1e30f, rm1 = -1e30f;
#pragma unroll
        for (int nf = 0; nf < 8; nf++) {
            rm0 = fmaxf(rm0, fmaxf(S[nf][0], S[nf][1]));
            rm1 = fmaxf(rm1, fmaxf(S[nf][2], S[nf][3]));
        }
        rm0 = fmaxf(rm0, __shfl_xor_sync(0xffffffffu, rm0, 1));
        rm0 = fmaxf(rm0, __shfl_xor_sync(0xffffffffu, rm0, 2));
        rm1 = fmaxf(rm1, __shfl_xor_sync(0xffffffffu, rm1, 1));
        rm1 = fmaxf(rm1, __shfl_xor_sync(0xffffffffu, rm1, 2));

        const float mn0 = fmaxf(m0r, rm0);
        const float mn1 = fmaxf(m1r, rm1);
        const float cr0 = ex2(m0r - mn0);
        const float cr1 = ex2(m1r - mn1);
        m0r = mn0; m1r = mn1;

        float rs0 = 0.f, rs1 = 0.f;
#pragma unroll
        for (int nf = 0; nf < 8; nf++) {
            S[nf][0] = ex2(S[nf][0] - mn0);
            S[nf][1] = ex2(S[nf][1] - mn0);
            S[nf][2] = ex2(S[nf][2] - mn1);
            S[nf][3] = ex2(S[nf][3] - mn1);
            rs0 += S[nf][0] + S[nf][1];
            rs1 += S[nf][2] + S[nf][3];
        }
        rs0 += __shfl_xor_sync(0xffffffffu, rs0, 1);
        rs0 += __shfl_xor_sync(0xffffffffu, rs0, 2);
        rs1 += __shfl_xor_sync(0xffffffffu, rs1, 1);
        rs1 += __shfl_xor_sync(0xffffffffu, rs1, 2);
        l0r = l0r * cr0 + rs0;
        l1r = l1r * cr1 + rs1;

#pragma unroll
        for (int nf = 0; nf < 8; nf++) {
            O[nf][0] *= cr0; O[nf][1] *= cr0;
            O[nf][2] *= cr1; O[nf][3] *= cr1;
        }

        // ---- O += Ph (Vh + Vl) ----
#pragma unroll
        for (int kf = 0; kf < 4; kf++) {
            uint32_t pah[4];
#pragma unroll
            for (int half = 0; half < 2; half++) {
                __half2 t01 = __floats2half2_rn(S[2 * kf + half][0], S[2 * kf + half][1]);
                __half2 t23 = __floats2half2_rn(S[2 * kf + half][2], S[2 * kf + half][3]);
                pah[2 * half + 0] = *reinterpret_cast<uint32_t*>(&t01);
                pah[2 * half + 1] = *reinterpret_cast<uint32_t*>(&t23);
            }
            uint32_t vh[8][2], vl[8][2];
#pragma unroll
            for (int bi = 0; bi < 4; bi++) {
                uint32_t vrow = kf * 16 + (quad & 1) * 8 + qr;
                uint32_t vcb = bi * 32 + (quad >> 1) * 16;
                uint32_t o = swz(vrow, vcb);
                ldmx4t(vh[bi * 2][0], vh[bi * 2][1], vh[bi * 2 + 1][0],
                       vh[bi * 2 + 1][1], tVh + o);
                ldmx4t(vl[bi * 2][0], vl[bi * 2][1], vl[bi * 2 + 1][0],
                       vl[bi * 2 + 1][1], tVl + o);
            }
#pragma unroll
            for (int nf = 0; nf < 8; nf++) {
                mma16816(O[nf][0], O[nf][1], O[nf][2], O[nf][3],
                         pah[0], pah[1], pah[2], pah[3], vh[nf][0], vh[nf][1]);
                mma16816(O[nf][0], O[nf][1], O[nf][2], O[nf][3],
                         pah[0], pah[1], pah[2], pah[3], vl[nf][0], vl[nf][1]);
            }
        }
    }

    // ---- epilogue: normalize, store hi only (proj is 1-term) ----
    const float li0 = 1.f / l0r;
    const float li1 = 1.f / l1r;
    const size_t r0 = (size_t)(b * T_) + row_lo;
    const int colb = h * D_ + 2 * (lane & 3);
#pragma unroll
    for (int nf = 0; nf < 8; nf++) {
        const size_t c = colb + nf * 8;
        *reinterpret_cast<__half2*>(yh + r0 * C_ + c) =
            __floats2half2_rn(O[nf][0] * li0, O[nf][1] * li0);
        *reinterpret_cast<__half2*>(yh + (r0 + 8) * C_ + c) =
            __floats2half2_rn(O[nf][2] * li1, O[nf][3] * li1);
    }
}

// ---------------- launch ----------------
extern "C" void kernel_launch(void* const* d_in, const int* in_sizes, int n_in,
                              void* d_out, int out_size)
{
    const float* x      = (const float*)d_in[0];
    const float* w_attn = (const float*)d_in[1];
    const float* w_proj = (const float*)d_in[2];
    float* out = (float*)d_out;

    __half *xhi, *wahi, *wphi, *qkvh, *qkvl, *yhi;
    cudaGetSymbolAddress((void**)&xhi, g_xhi);
    cudaGetSymbolAddress((void**)&wahi, g_wahi);
    cudaGetSymbolAddress((void**)&wphi, g_wphi);
    cudaGetSymbolAddress((void**)&qkvh, g_qkvh);
    cudaGetSymbolAddress((void**)&qkvl, g_qkvl);
    cudaGetSymbolAddress((void**)&yhi, g_yhi);

    cudaFuncSetAttribute(gemm_mma, cudaFuncAttributeMaxDynamicSharedMemorySize, GEMM_SMEM);
    cudaFuncSetAttribute(flash_attn_mma, cudaFuncAttributeMaxDynamicSharedMemorySize, AT_SMEM);

    {
        int n4 = M_ROWS * C_ / 4;
        trunc_f16<<<(n4 + 255) / 256, 256>>>((const float4*)x, (__half2*)xhi, n4);
    }
    {
        int n4 = C3_ * C_ / 4;
        trunc_f16<<<(n4 + 255) / 256, 256>>>((const float4*)w_attn, (__half2*)wahi, n4);
    }
    {
        int n4 = C_ * C_ / 4;
        trunc_f16<<<(n4 + 255) / 256, 256>>>((const float4*)w_proj, (__half2*)wphi, n4);
    }

    // 1) QKV = xh @ wah^T (1-term fp16): write fp16 hi/lo
    {
        dim3 g(C3_ / 64, M_ROWS / 128);
        gemm_mma<<<g, 128, GEMM_SMEM>>>(xhi, wahi,
                                        nullptr, qkvh, qkvl, 1, M_ROWS, C3_, C_);
    }
    // 2) tensor-core flash attention (2-term fp16), writes yh only
    {
        dim3 g(T_ / 64, H_, B_);
        flash_attn_mma<<<g, 128, AT_SMEM>>>(qkvh, qkvl, yhi);
    }
    // 3) out = yh @ wph^T (1-term fp16, fp32 out)
    {
        dim3 g(C_ / 64, M_ROWS / 128);
        gemm_mma<<<g, 128, GEMM_SMEM>>>(yhi, wphi,
                                        out, nullptr, nullptr, 0, M_ROWS, C_, C_);
    }
}

// round 15
// speedup vs baseline: 10.5877x; 1.3133x over previous
#include <cuda_runtime.h>
#include <cuda_fp16.h>
#include <cstdint>

#define B_ 4
#define T_ 2048
#define C_ 1024
#define H_ 16
#define D_ 64
#define C3_ 3072
#define M_ROWS (B_ * T_)

// ---------------- scratch (device globals: allocation-free) ----------------
__device__ __half g_xhi[(size_t)M_ROWS * C_];
__device__ __half g_wahi[(size_t)C3_ * C_];
__device__ __half g_wphi[(size_t)C_ * C_];
__device__ __half g_qkvh[(size_t)M_ROWS * C3_];
__device__ __half g_yhi[(size_t)M_ROWS * C_];

// ---------------- helpers ----------------
__device__ __forceinline__ uint32_t smem_u32(const void* p) {
    uint32_t a;
    asm("{ .reg .u64 t; cvta.to.shared.u64 t, %1; cvt.u32.u64 %0, t; }"
        : "=r"(a) : "l"(p));
    return a;
}
__device__ __forceinline__ void cp_async16(uint32_t dst, const void* src) {
    asm volatile("cp.async.cg.shared.global [%0], [%1], 16;" :: "r"(dst), "l"(src));
}
__device__ __forceinline__ void cp_commit() {
    asm volatile("cp.async.commit_group;" ::: "memory");
}
__device__ __forceinline__ void cp_wait2() {
    asm volatile("cp.async.wait_group 2;" ::: "memory");
}
__device__ __forceinline__ void cp_wait3() {
    asm volatile("cp.async.wait_group 3;" ::: "memory");
}
__device__ __forceinline__ void ldmx4(uint32_t& r0, uint32_t& r1, uint32_t& r2,
                                      uint32_t& r3, uint32_t addr) {
    asm volatile("ldmatrix.sync.aligned.m8n8.x4.shared.b16 {%0,%1,%2,%3}, [%4];"
                 : "=r"(r0), "=r"(r1), "=r"(r2), "=r"(r3) : "r"(addr));
}
__device__ __forceinline__ void ldmx4t(uint32_t& r0, uint32_t& r1, uint32_t& r2,
                                       uint32_t& r3, uint32_t addr) {
    asm volatile("ldmatrix.sync.aligned.m8n8.x4.trans.shared.b16 {%0,%1,%2,%3}, [%4];"
                 : "=r"(r0), "=r"(r1), "=r"(r2), "=r"(r3) : "r"(addr));
}
__device__ __forceinline__ void mma16816(float& d0, float& d1, float& d2, float& d3,
                                         uint32_t a0, uint32_t a1, uint32_t a2, uint32_t a3,
                                         uint32_t b0, uint32_t b1) {
    asm volatile("mma.sync.aligned.m16n8k16.row.col.f32.f16.f16.f32 "
                 "{%0,%1,%2,%3}, {%4,%5,%6,%7}, {%8,%9}, {%0,%1,%2,%3};"
                 : "+f"(d0), "+f"(d1), "+f"(d2), "+f"(d3)
                 : "r"(a0), "r"(a1), "r"(a2), "r"(a3), "r"(b0), "r"(b1));
}
__device__ __forceinline__ float ex2(float x) {
    float y;
    asm("ex2.approx.ftz.f32 %0, %1;" : "=f"(y) : "f"(x));
    return y;
}
// swizzled byte offset: row-major 128B rows, xor bits 4-6 by row&7
__device__ __forceinline__ uint32_t swz(uint32_t row, uint32_t kb) {
    return row * 128u + (kb ^ ((row & 7u) * 16u));
}

// ---------------- fp32 -> fp16 ----------------
__global__ __launch_bounds__(256)
void trunc_f16(const float4* __restrict__ in, __half2* __restrict__ hi, int n4)
{
    int i = blockIdx.x * 256 + threadIdx.x;
    if (i >= n4) return;
    float4 v = in[i];
    hi[2 * i + 0] = __floats2half2_rn(v.x, v.y);
    hi[2 * i + 1] = __floats2half2_rn(v.z, v.w);
}

// ---------------- mma.sync GEMM: C = Ah @ Wh^T (1-term fp16, 4-stage) ------
// Tile 128x64 per CTA, 128 threads (4 warps: 2M x 2N, warp 64x32).
// Stage = {A 16KB, B 8KB} = 24KB; 4 stages = 96KB/CTA -> 2 CTAs/SM.
#define TILE_A 16384           // 128 rows x 128B
#define TILE_BB 8192           // 64 rows x 128B
#define G_STAGE (TILE_A + TILE_BB)       // 24KB
#define GEMM_SMEM (4 * G_STAGE)          // 96KB

__global__ __launch_bounds__(128, 2)
void gemm_mma(const __half* __restrict__ Ahi, const __half* __restrict__ Bhi,
              float* __restrict__ Cout, __half* __restrict__ Chi,
              int split_out, int M, int N, int K)
{
    extern __shared__ char smem[];
    const uint32_t sbase = smem_u32(smem);
    const int tid = threadIdx.x;
    const int wid = tid >> 5;
    const int lane = tid & 31;
    const int wm = wid & 1;          // M offset 0/64
    const int wn = wid >> 1;         // N offset 0/32
    const size_t m0 = (size_t)blockIdx.y * 128;
    const size_t n0 = (size_t)blockIdx.x * 64;
    const int quad = lane >> 3;
    const int qr = lane & 7;

    float acc[4][4][4];
#pragma unroll
    for (int i = 0; i < 4; i++)
#pragma unroll
        for (int j = 0; j < 4; j++)
#pragma unroll
            for (int r = 0; r < 4; r++) acc[i][j][r] = 0.f;

    const int NCH = K >> 6;

    auto issue_chunk = [&](int ch, int st) {
        const int k0 = ch * 64;
        char* base = smem + st * G_STAGE;
#pragma unroll
        for (int it = 0; it < 8; it++) {       // A: 1024 16B chunks
            int idx = it * 128 + tid;
            uint32_t row = idx >> 3, c16 = idx & 7;
            cp_async16(smem_u32(base + swz(row, c16 * 16u)),
                       Ahi + (m0 + row) * (size_t)K + k0 + c16 * 8);
        }
#pragma unroll
        for (int it = 0; it < 4; it++) {       // B: 512 chunks
            int idx = it * 128 + tid;
            uint32_t row = idx >> 3, c16 = idx & 7;
            cp_async16(smem_u32(base + TILE_A + swz(row, c16 * 16u)),
                       Bhi + (n0 + row) * (size_t)K + k0 + c16 * 8);
        }
        cp_commit();
    };

    issue_chunk(0, 0);
    issue_chunk(1, 1);
    issue_chunk(2, 2);

    for (int ch = 0; ch < NCH; ch++) {
        const int s = ch & 3;
        cp_wait2();            // chunk ch resident (ch+1, ch+2 may pend)
        __syncthreads();       // all warps done with ch-1 -> stage (ch+3)&3 free
        if (ch + 3 < NCH) issue_chunk(ch + 3, (ch + 3) & 3);
        else cp_commit();

        const uint32_t tA = sbase + s * G_STAGE;
        const uint32_t tB = tA + TILE_A;

#pragma unroll
        for (int kk = 0; kk < 4; kk++) {
            const uint32_t kb = kk * 32;
            uint32_t ah[4][4];
#pragma unroll
            for (int mi = 0; mi < 4; mi++) {
                uint32_t arow = wm * 64 + mi * 16 + (quad & 1) * 8 + qr;
                uint32_t akb = kb + (quad >> 1) * 16;
                ldmx4(ah[mi][0], ah[mi][1], ah[mi][2], ah[mi][3], tA + swz(arow, akb));
            }
            uint32_t bh[4][2];
#pragma unroll
            for (int bi = 0; bi < 2; bi++) {
                uint32_t brow = wn * 32 + bi * 16 + (quad >> 1) * 8 + qr;
                uint32_t bkb = kb + (quad & 1) * 16;
                ldmx4(bh[bi * 2][0], bh[bi * 2][1], bh[bi * 2 + 1][0], bh[bi * 2 + 1][1],
                      tB + swz(brow, bkb));
            }
#pragma unroll
            for (int mi = 0; mi < 4; mi++) {
#pragma unroll
                for (int ni = 0; ni < 4; ni++) {
                    float* d = acc[mi][ni];
                    mma16816(d[0], d[1], d[2], d[3],
                             ah[mi][0], ah[mi][1], ah[mi][2], ah[mi][3],
                             bh[ni][0], bh[ni][1]);
                }
            }
        }
    }

    const int g = lane >> 2;
    const int ti = lane & 3;
#pragma unroll
    for (int mi = 0; mi < 4; mi++) {
#pragma unroll
        for (int ni = 0; ni < 4; ni++) {
            size_t row = m0 + wm * 64 + mi * 16 + g;
            size_t col = n0 + wn * 32 + ni * 8 + 2 * ti;
            float* a = acc[mi][ni];
            if (split_out) {
                *reinterpret_cast<__half2*>(Chi + row * N + col) =
                    __floats2half2_rn(a[0], a[1]);
                *reinterpret_cast<__half2*>(Chi + (row + 8) * N + col) =
                    __floats2half2_rn(a[2], a[3]);
            } else {
                *reinterpret_cast<float2*>(Cout + row * N + col) =
                    make_float2(a[0], a[1]);
                *reinterpret_cast<float2*>(Cout + (row + 8) * N + col) =
                    make_float2(a[2], a[3]);
            }
        }
    }
}

// ---------------- tensor-core flash attention (causal, 1-term fp16) --------
// CTA: 64 q rows, 4 warps x 16 rows, 128 threads. KV tiles of 64, 4-stage.
// SMEM: Qh 8KB + 4 x 16KB KV = 72KB -> 2 CTAs/SM. Single barrier/tile.
// S = Qh Kh^T ; O += Ph Vh   (fp32 accumulate throughout)
#define AT_TILE 8192          // 64 rows x 128B
#define AT_STAGE (2 * AT_TILE)
#define AT_QB 8192
#define AT_SMEM (AT_QB + 4 * AT_STAGE)
#define SCALE_LOG2E 0.1803368801111204f   // (1/8) * log2(e)

__global__ __launch_bounds__(128, 2)
void flash_attn_mma(const __half* __restrict__ qh, __half* __restrict__ yh)
{
    extern __shared__ char smem[];
    const uint32_t sbase = smem_u32(smem);
    const int tid = threadIdx.x;
    const int wid = tid >> 5;
    const int lane = tid & 31;
    const int quad = lane >> 3;
    const int qr = lane & 7;
    const int b = blockIdx.z;
    const int h = blockIdx.y;
    const int qt = gridDim.x - 1 - blockIdx.x;
    const int q0 = qt * 64;
    const int nt = qt + 1;

    const size_t bbase = (size_t)(b * T_) * C3_;
    const __half* qsh = qh + bbase + h * D_;
    const __half* ksh = qh + bbase + C_ + h * D_;
    const __half* vsh = qh + bbase + 2 * C_ + h * D_;

    auto issue_kv = [&](int t, int stage) {
        const int j0 = t * 64;
        const uint32_t kvb = sbase + AT_QB + stage * AT_STAGE;
#pragma unroll
        for (int it = 0; it < 4; it++) {
            int idx = it * 128 + tid;               // 512 chunks per tile
            uint32_t r = idx >> 3, c16 = idx & 7;
            size_t off = (size_t)(j0 + r) * C3_ + c16 * 8;
            uint32_t so = swz(r, c16 * 16u);
            cp_async16(kvb + 0 * AT_TILE + so, ksh + off);
            cp_async16(kvb + 1 * AT_TILE + so, vsh + off);
        }
        cp_commit();
    };

    // group 0: Qh (64 rows x 8 chunks = 512)
#pragma unroll
    for (int it = 0; it < 4; it++) {
        int idx = it * 128 + tid;
        uint32_t r = idx >> 3, c16 = idx & 7;
        cp_async16(sbase + swz(r, c16 * 16u), qsh + (size_t)(q0 + r) * C3_ + c16 * 8);
    }
    cp_commit();
    issue_kv(0, 0);
    if (nt > 1) issue_kv(1, 1); else cp_commit();
    if (nt > 2) issue_kv(2, 2); else cp_commit();
    cp_wait3();       // Q resident (3 kv groups may pend)
    __syncthreads();

    uint32_t Qh[4][4];
#pragma unroll
    for (int kf = 0; kf < 4; kf++) {
        uint32_t arow = wid * 16 + (quad & 1) * 8 + qr;
        uint32_t akb = kf * 32 + (quad >> 1) * 16;
        ldmx4(Qh[kf][0], Qh[kf][1], Qh[kf][2], Qh[kf][3], sbase + swz(arow, akb));
    }

    float O[8][4];
#pragma unroll
    for (int i = 0; i < 8; i++)
#pragma unroll
        for (int r = 0; r < 4; r++) O[i][r] = 0.f;
    float m0r = -1e30f, m1r = -1e30f, l0r = 0.f, l1r = 0.f;
    const int row_lo = q0 + wid * 16 + (lane >> 2);

    for (int t = 0; t < nt; t++) {
        const int s = t & 3;
        cp_wait2();            // kv tile t resident (2 newer may pend)
        __syncthreads();       // stage (t+3)&3 free (all warps done with t-1)
        if (t + 3 < nt) issue_kv(t + 3, (t + 3) & 3);
        else cp_commit();

        const int j0 = t * 64;
        const uint32_t stage = sbase + AT_QB + s * AT_STAGE;
        const uint32_t tKh = stage + 0 * AT_TILE;
        const uint32_t tVh = stage + 1 * AT_TILE;

        // ---- S = Qh Kh^T ----
        float S[8][4];
#pragma unroll
        for (int i = 0; i < 8; i++)
#pragma unroll
            for (int r = 0; r < 4; r++) S[i][r] = 0.f;

#pragma unroll
        for (int kf = 0; kf < 4; kf++) {
            uint32_t bh[8][2];
#pragma unroll
            for (int bi = 0; bi < 4; bi++) {
                uint32_t brow = bi * 16 + (quad >> 1) * 8 + qr;
                uint32_t bkb = kf * 32 + (quad & 1) * 16;
                ldmx4(bh[bi * 2][0], bh[bi * 2][1], bh[bi * 2 + 1][0], bh[bi * 2 + 1][1],
                      tKh + swz(brow, bkb));
            }
#pragma unroll
            for (int nf = 0; nf < 8; nf++) {
                mma16816(S[nf][0], S[nf][1], S[nf][2], S[nf][3],
                         Qh[kf][0], Qh[kf][1], Qh[kf][2], Qh[kf][3],
                         bh[nf][0], bh[nf][1]);
            }
        }

        // scale + causal mask
#pragma unroll
        for (int nf = 0; nf < 8; nf++)
#pragma unroll
            for (int r = 0; r < 4; r++) S[nf][r] *= SCALE_LOG2E;

        if (j0 + 63 > q0 + wid * 16) {
            const int kvb = j0 + 2 * (lane & 3);
#pragma unroll
            for (int nf = 0; nf < 8; nf++) {
                const int kv = kvb + nf * 8;
                if (kv     > row_lo)     S[nf][0] = -1e30f;
                if (kv + 1 > row_lo)     S[nf][1] = -1e30f;
                if (kv     > row_lo + 8) S[nf][2] = -1e30f;
                if (kv + 1 > row_lo + 8) S[nf][3] = -1e30f;
            }
        }

        // row max
        float rm0 = -1e30f, rm1 = -1e30f;
#pragma unroll
        for (int nf = 0; nf < 8; nf++) {
            rm0 = fmaxf(rm0, fmaxf(S[nf][0], S[nf][1]));
            rm1 = fmaxf(rm1, fmaxf(S[nf][2], S[nf][3]));
        }
        rm0 = fmaxf(rm0, __shfl_xor_sync(0xffffffffu, rm0, 1));
        rm0 = fmaxf(rm0, __shfl_xor_sync(0xffffffffu, rm0, 2));
        rm1 = fmaxf(rm1, __shfl_xor_sync(0xffffffffu, rm1, 1));
        rm1 = fmaxf(rm1, __shfl_xor_sync(0xffffffffu, rm1, 2));

        const float mn0 = fmaxf(m0r, rm0);
        const float mn1 = fmaxf(m1r, rm1);
        const float cr0 = ex2(m0r - mn0);
        const float cr1 = ex2(m1r - mn1);
        m0r = mn0; m1r = mn1;

        float rs0 = 0.f, rs1 = 0.f;
#pragma unroll
        for (int nf = 0; nf < 8; nf++) {
            S[nf][0] = ex2(S[nf][0] - mn0);
            S[nf][1] = ex2(S[nf][1] - mn0);
            S[nf][2] = ex2(S[nf][2] - mn1);
            S[nf][3] = ex2(S[nf][3] - mn1);
            rs0 += S[nf][0] + S[nf][1];
            rs1 += S[nf][2] + S[nf][3];
        }
        rs0 += __shfl_xor_sync(0xffffffffu, rs0, 1);
        rs0 += __shfl_xor_sync(0xffffffffu, rs0, 2);
        rs1 += __shfl_xor_sync(0xffffffffu, rs1, 1);
        rs1 += __shfl_xor_sync(0xffffffffu, rs1, 2);
        l0r = l0r * cr0 + rs0;
        l1r = l1r * cr1 + rs1;

#pragma unroll
        for (int nf = 0; nf < 8; nf++) {
            O[nf][0] *= cr0; O[nf][1] *= cr0;
            O[nf][2] *= cr1; O[nf][3] *= cr1;
        }

        // ---- O += Ph Vh ----
#pragma unroll
        for (int kf = 0; kf < 4; kf++) {
            uint32_t pah[4];
#pragma unroll
            for (int half = 0; half < 2; half++) {
                __half2 t01 = __floats2half2_rn(S[2 * kf + half][0], S[2 * kf + half][1]);
                __half2 t23 = __floats2half2_rn(S[2 * kf + half][2], S[2 * kf + half][3]);
                pah[2 * half + 0] = *reinterpret_cast<uint32_t*>(&t01);
                pah[2 * half + 1] = *reinterpret_cast<uint32_t*>(&t23);
            }
            uint32_t vh[8][2];
#pragma unroll
            for (int bi = 0; bi < 4; bi++) {
                uint32_t vrow = kf * 16 + (quad & 1) * 8 + qr;
                uint32_t vcb = bi * 32 + (quad >> 1) * 16;
                ldmx4t(vh[bi * 2][0], vh[bi * 2][1], vh[bi * 2 + 1][0],
                       vh[bi * 2 + 1][1], tVh + swz(vrow, vcb));
            }
#pragma unroll
            for (int nf = 0; nf < 8; nf++) {
                mma16816(O[nf][0], O[nf][1], O[nf][2], O[nf][3],
                         pah[0], pah[1], pah[2], pah[3], vh[nf][0], vh[nf][1]);
            }
        }
    }

    // ---- epilogue: normalize, store fp16 ----
    const float li0 = 1.f / l0r;
    const float li1 = 1.f / l1r;
    const size_t r0 = (size_t)(b * T_) + row_lo;
    const int colb = h * D_ + 2 * (lane & 3);
#pragma unroll
    for (int nf = 0; nf < 8; nf++) {
        const size_t c = colb + nf * 8;
        *reinterpret_cast<__half2*>(yh + r0 * C_ + c) =
            __floats2half2_rn(O[nf][0] * li0, O[nf][1] * li0);
        *reinterpret_cast<__half2*>(yh + (r0 + 8) * C_ + c) =
            __floats2half2_rn(O[nf][2] * li1, O[nf][3] * li1);
    }
}

// ---------------- launch ----------------
extern "C" void kernel_launch(void* const* d_in, const int* in_sizes, int n_in,
                              void* d_out, int out_size)
{
    const float* x      = (const float*)d_in[0];
    const float* w_attn = (const float*)d_in[1];
    const float* w_proj = (const float*)d_in[2];
    float* out = (float*)d_out;

    __half *xhi, *wahi, *wphi, *qkvh, *yhi;
    cudaGetSymbolAddress((void**)&xhi, g_xhi);
    cudaGetSymbolAddress((void**)&wahi, g_wahi);
    cudaGetSymbolAddress((void**)&wphi, g_wphi);
    cudaGetSymbolAddress((void**)&qkvh, g_qkvh);
    cudaGetSymbolAddress((void**)&yhi, g_yhi);

    cudaFuncSetAttribute(gemm_mma, cudaFuncAttributeMaxDynamicSharedMemorySize, GEMM_SMEM);
    cudaFuncSetAttribute(flash_attn_mma, cudaFuncAttributeMaxDynamicSharedMemorySize, AT_SMEM);

    {
        int n4 = M_ROWS * C_ / 4;
        trunc_f16<<<(n4 + 255) / 256, 256>>>((const float4*)x, (__half2*)xhi, n4);
    }
    {
        int n4 = C3_ * C_ / 4;
        trunc_f16<<<(n4 + 255) / 256, 256>>>((const float4*)w_attn, (__half2*)wahi, n4);
    }
    {
        int n4 = C_ * C_ / 4;
        trunc_f16<<<(n4 + 255) / 256, 256>>>((const float4*)w_proj, (__half2*)wphi, n4);
    }

    // 1) QKV = xh @ wah^T (1-term fp16) -> fp16
    {
        dim3 g(C3_ / 64, M_ROWS / 128);
        gemm_mma<<<g, 128, GEMM_SMEM>>>(xhi, wahi, nullptr, qkvh, 1, M_ROWS, C3_, C_);
    }
    // 2) tensor-core flash attention (1-term fp16) -> fp16
    {
        dim3 g(T_ / 64, H_, B_);
        flash_attn_mma<<<g, 128, AT_SMEM>>>(qkvh, yhi);
    }
    // 3) out = yh @ wph^T (1-term fp16, fp32 out)
    {
        dim3 g(C_ / 64, M_ROWS / 128);
        gemm_mma<<<g, 128, GEMM_SMEM>>>(yhi, wphi, out, nullptr, 0, M_ROWS, C_, C_);
    }
}